// round 2
// baseline (speedup 1.0000x reference)
#include <cuda_runtime.h>

#define N_NODES 8192
#define M_NBR   16
#define F_NODE  128
#define HID     512

// Scratch (allocation-free rule: __device__ globals)
__device__ float g_X[N_NODES * HID];
__device__ float g_Y[N_NODES * HID];
__device__ float g_dinv[N_NODES];

// ---------------------------------------------------------------------------
// deg[i] = (#valid neighbors) + 1 (self loop);  dinv = deg^{-1/2}
// NOTE: edge_fea_idx is int32 on device (JAX x64-disabled downcasts int64).
// ---------------------------------------------------------------------------
__global__ void deg_kernel(const int* __restrict__ idx) {
    int i = blockIdx.x * blockDim.x + threadIdx.x;
    if (i >= N_NODES) return;
    int cnt = 1;
#pragma unroll
    for (int k = 0; k < M_NBR; k++) cnt += (idx[i * M_NBR + k] >= 0) ? 1 : 0;
    g_dinv[i] = rsqrtf((float)cnt);
}

// ---------------------------------------------------------------------------
// C[M x HID] = A[M x K] * B[K x HID] + bias, optional ReLU.
// BM=128, BN=128, BK=8, 256 threads, 8x8 per thread.
// ---------------------------------------------------------------------------
template <int K, bool RELU>
__global__ __launch_bounds__(256, 1) void sgemm_kernel(
    const float* __restrict__ A, const float* __restrict__ B,
    const float* __restrict__ bias, float* __restrict__ C) {
    constexpr int BM = 128, BN = 128, BK = 8;
    __shared__ float As[BK][BM];
    __shared__ float Bs[BK][BN];

    const int tid = threadIdx.x;
    const int block_row = blockIdx.y * BM;
    const int block_col = blockIdx.x * BN;
    const int tx = tid % 16;  // col group
    const int ty = tid / 16;  // row group

    // A loads: 128 rows x 8 cols = 256 float4 (2 per row)
    const int aRow = tid >> 1;          // 0..127
    const int aCol = (tid & 1) * 4;     // 0 or 4
    // B loads: 8 rows x 128 cols = 256 float4
    const int bRow = tid >> 5;          // 0..7
    const int bCol = (tid & 31) * 4;    // 0..124

    float acc[8][8];
#pragma unroll
    for (int i = 0; i < 8; i++)
#pragma unroll
        for (int j = 0; j < 8; j++) acc[i][j] = 0.0f;

    for (int k0 = 0; k0 < K; k0 += BK) {
        float4 av = *(const float4*)&A[(long)(block_row + aRow) * K + k0 + aCol];
        As[aCol + 0][aRow] = av.x;
        As[aCol + 1][aRow] = av.y;
        As[aCol + 2][aRow] = av.z;
        As[aCol + 3][aRow] = av.w;
        float4 bv = *(const float4*)&B[(long)(k0 + bRow) * HID + block_col + bCol];
        *(float4*)&Bs[bRow][bCol] = bv;
        __syncthreads();

#pragma unroll
        for (int k = 0; k < BK; k++) {
            float ra[8], rb[8];
#pragma unroll
            for (int i = 0; i < 8; i++) ra[i] = As[k][ty * 8 + i];
#pragma unroll
            for (int j = 0; j < 8; j++) rb[j] = Bs[k][tx * 8 + j];
#pragma unroll
            for (int i = 0; i < 8; i++)
#pragma unroll
                for (int j = 0; j < 8; j++) acc[i][j] += ra[i] * rb[j];
        }
        __syncthreads();
    }

#pragma unroll
    for (int i = 0; i < 8; i++) {
        const int r = block_row + ty * 8 + i;
#pragma unroll
        for (int j = 0; j < 8; j += 4) {
            const int c = block_col + tx * 8 + j;
            float4 v;
            v.x = acc[i][j + 0] + bias[c + 0];
            v.y = acc[i][j + 1] + bias[c + 1];
            v.z = acc[i][j + 2] + bias[c + 2];
            v.w = acc[i][j + 3] + bias[c + 3];
            if (RELU) {
                v.x = fmaxf(v.x, 0.0f);
                v.y = fmaxf(v.y, 0.0f);
                v.z = fmaxf(v.z, 0.0f);
                v.w = fmaxf(v.w, 0.0f);
            }
            *(float4*)&C[(long)r * HID + c] = v;
        }
    }
}

// ---------------------------------------------------------------------------
// Y[i,:] = dinv[i] * ( sum_{valid j} dinv[j] * X[j,:] + dinv[i] * X[i,:] )
// One block per row, 128 threads, float4 per thread (128*4 = 512 cols).
// ---------------------------------------------------------------------------
__global__ __launch_bounds__(128) void spmm_kernel(
    const int* __restrict__ idx, const float* __restrict__ X,
    float* __restrict__ Y) {
    const int i = blockIdx.x;
    const int t = threadIdx.x;

    __shared__ int s_j[M_NBR];
    __shared__ float s_dj[M_NBR];
    if (t < M_NBR) {
        int j = idx[i * M_NBR + t];
        s_j[t] = j;
        s_dj[t] = (j >= 0) ? g_dinv[j] : 0.0f;
    }
    __syncthreads();

    const float di = g_dinv[i];
    float4 v = ((const float4*)&X[(long)i * HID])[t];
    float4 acc = make_float4(v.x * di, v.y * di, v.z * di, v.w * di);

#pragma unroll
    for (int k = 0; k < M_NBR; k++) {
        int j = s_j[k];
        if (j < 0) continue;
        float dj = s_dj[k];
        float4 w = ((const float4*)&X[(long)j * HID])[t];
        acc.x += dj * w.x;
        acc.y += dj * w.y;
        acc.z += dj * w.z;
        acc.w += dj * w.w;
    }
    acc.x *= di; acc.y *= di; acc.z *= di; acc.w *= di;
    ((float4*)&Y[(long)i * HID])[t] = acc;
}

// ---------------------------------------------------------------------------
extern "C" void kernel_launch(void* const* d_in, const int* in_sizes, int n_in,
                              void* d_out, int out_size) {
    const float* node_in = (const float*)d_in[0];
    const int*   edges   = (const int*)d_in[1];
    const float* W_emb   = (const float*)d_in[2];
    const float* b_emb   = (const float*)d_in[3];
    const float* W1      = (const float*)d_in[4];
    const float* b1      = (const float*)d_in[5];
    const float* W2      = (const float*)d_in[6];
    const float* b2      = (const float*)d_in[7];
    const float* W3      = (const float*)d_in[8];
    const float* b3      = (const float*)d_in[9];
    float* out = (float*)d_out;

    float* X; cudaGetSymbolAddress((void**)&X, g_X);
    float* Y; cudaGetSymbolAddress((void**)&Y, g_Y);

    // 1) degrees
    deg_kernel<<<(N_NODES + 255) / 256, 256>>>(edges);

    dim3 gemm_grid(HID / 128, N_NODES / 128);

    // 2) X = node_in @ W_emb + b_emb
    sgemm_kernel<F_NODE, false><<<gemm_grid, 256>>>(node_in, W_emb, b_emb, X);

    // 3) layer 1: Y = A_norm X ; X = relu(Y W1 + b1)
    spmm_kernel<<<N_NODES, 128>>>(edges, X, Y);
    sgemm_kernel<HID, true><<<gemm_grid, 256>>>(Y, W1, b1, X);

    // 4) layer 2
    spmm_kernel<<<N_NODES, 128>>>(edges, X, Y);
    sgemm_kernel<HID, true><<<gemm_grid, 256>>>(Y, W2, b2, X);

    // 5) layer 3 (no relu) -> d_out
    spmm_kernel<<<N_NODES, 128>>>(edges, X, Y);
    sgemm_kernel<HID, false><<<gemm_grid, 256>>>(Y, W3, b3, out);
}

// round 4
// speedup vs baseline: 1.8205x; 1.8205x over previous
#include <cuda_runtime.h>
#include <cuda_bf16.h>
#include <cstdint>

#define N_NODES 8192
#define M_NBR   16
#define F_NODE  128
#define HID     512

// K-split-3 layout: A' = [Ah | Ah | Al], B' = [Bh | Bl | Bh] along K.
#define K3_HID  (3 * HID)     // 1536
#define K3_EMB  (3 * F_NODE)  // 384

// ---------------- scratch (__device__ globals; no allocations) ----------------
__device__ __nv_bfloat16 g_A[N_NODES * K3_HID];    // split activations (also used with stride K3_EMB)
__device__ float         g_X[N_NODES * HID];       // fp32 activations between stages
__device__ float         g_dinv[N_NODES];
#define WOFF_1 0
#define WOFF_2 (HID * K3_HID)
#define WOFF_3 (2 * HID * K3_HID)
#define WOFF_E (3 * HID * K3_HID)
__device__ __nv_bfloat16 g_W[3 * HID * K3_HID + HID * K3_EMB];

// ---------------- PTX helpers (compute_103-safe: no tcgen05) ----------------
__device__ __forceinline__ uint32_t smem_to_u32(const void* p) {
    uint32_t a;
    asm("{ .reg .u64 t; cvta.to.shared.u64 t, %1; cvt.u32.u64 %0, t; }" : "=r"(a) : "l"(p));
    return a;
}
__device__ __forceinline__ void cp_async16(uint32_t saddr, const void* gptr) {
    asm volatile("cp.async.cg.shared.global [%0], [%1], 16;" :: "r"(saddr), "l"(gptr));
}
#define CP_COMMIT() asm volatile("cp.async.commit_group;" ::: "memory")
#define CP_WAIT0()  asm volatile("cp.async.wait_group 0;" ::: "memory")
#define CP_WAIT1()  asm volatile("cp.async.wait_group 1;" ::: "memory")

__device__ __forceinline__ void ldsm_x4(uint32_t& r0, uint32_t& r1, uint32_t& r2,
                                        uint32_t& r3, uint32_t addr) {
    asm volatile("ldmatrix.sync.aligned.m8n8.x4.shared.b16 {%0,%1,%2,%3}, [%4];"
                 : "=r"(r0), "=r"(r1), "=r"(r2), "=r"(r3) : "r"(addr));
}
__device__ __forceinline__ void mma16816(float* d, const uint32_t* a, const uint32_t* b) {
    asm volatile(
        "mma.sync.aligned.m16n8k16.row.col.f32.bf16.bf16.f32 "
        "{%0,%1,%2,%3}, {%4,%5,%6,%7}, {%8,%9}, {%0,%1,%2,%3};"
        : "+f"(d[0]), "+f"(d[1]), "+f"(d[2]), "+f"(d[3])
        : "r"(a[0]), "r"(a[1]), "r"(a[2]), "r"(a[3]), "r"(b[0]), "r"(b[1]));
}

__device__ __forceinline__ void split_bf16(float v, __nv_bfloat16& h, __nv_bfloat16& l) {
    h = __float2bfloat16(v);
    l = __float2bfloat16(v - __bfloat162float(h));
}

// ---------------------------------------------------------------------------
// dinv = (1 + #valid)^{-1/2}
// ---------------------------------------------------------------------------
__global__ void deg_kernel(const int* __restrict__ idx) {
    int i = blockIdx.x * blockDim.x + threadIdx.x;
    if (i >= N_NODES) return;
    int cnt = 1;
#pragma unroll
    for (int k = 0; k < M_NBR; k++) cnt += (idx[i * M_NBR + k] >= 0) ? 1 : 0;
    g_dinv[i] = rsqrtf((float)cnt);
}

// ---------------------------------------------------------------------------
// node_in (fp32, stride F_NODE) -> g_A split, row stride K3_EMB: [hi | hi | lo]
// ---------------------------------------------------------------------------
__global__ void convert_in_kernel(const float* __restrict__ src) {
    int total = N_NODES * F_NODE;
    for (int i = blockIdx.x * blockDim.x + threadIdx.x; i < total;
         i += gridDim.x * blockDim.x) {
        int r = i / F_NODE, c = i % F_NODE;
        __nv_bfloat16 h, l;
        split_bf16(src[i], h, l);
        size_t base = (size_t)r * K3_EMB;
        g_A[base + c] = h;
        g_A[base + F_NODE + c] = h;
        g_A[base + 2 * F_NODE + c] = l;
    }
}

// ---------------------------------------------------------------------------
// W[K][N] fp32 -> out[N][3K] bf16: [hi | lo | hi]  (B' = [Bh | Bl | Bh])
// ---------------------------------------------------------------------------
__global__ void wsplit_kernel(const float* __restrict__ W, int K, int N,
                              __nv_bfloat16* __restrict__ o) {
    int total = K * N;
    for (int i = blockIdx.x * blockDim.x + threadIdx.x; i < total;
         i += gridDim.x * blockDim.x) {
        int k = i / N, n = i % N;
        __nv_bfloat16 h, l;
        split_bf16(W[i], h, l);
        size_t base = (size_t)n * (3 * K);
        o[base + k] = h;
        o[base + K + k] = l;
        o[base + 2 * K + k] = h;
    }
}

// ---------------------------------------------------------------------------
// SpMM: fp32 in (g_X), writes split bf16 rows [hi | hi | lo] stride K3_HID
// ---------------------------------------------------------------------------
__global__ __launch_bounds__(128) void spmm_kernel(const int* __restrict__ idx,
                                                   const float* __restrict__ X) {
    const int i = blockIdx.x;
    const int t = threadIdx.x;

    __shared__ int s_j[M_NBR];
    __shared__ float s_dj[M_NBR];
    if (t < M_NBR) {
        int j = idx[i * M_NBR + t];
        s_j[t] = j;
        s_dj[t] = (j >= 0) ? g_dinv[j] : 0.0f;
    }
    __syncthreads();

    const float di = g_dinv[i];
    float4 v = ((const float4*)&X[(size_t)i * HID])[t];
    float4 acc = make_float4(v.x * di, v.y * di, v.z * di, v.w * di);

#pragma unroll
    for (int k = 0; k < M_NBR; k++) {
        int j = s_j[k];
        if (j < 0) continue;
        float dj = s_dj[k];
        float4 w = ((const float4*)&X[(size_t)j * HID])[t];
        acc.x += dj * w.x;
        acc.y += dj * w.y;
        acc.z += dj * w.z;
        acc.w += dj * w.w;
    }
    acc.x *= di; acc.y *= di; acc.z *= di; acc.w *= di;

    __nv_bfloat16 h[4], l[4];
    split_bf16(acc.x, h[0], l[0]);
    split_bf16(acc.y, h[1], l[1]);
    split_bf16(acc.z, h[2], l[2]);
    split_bf16(acc.w, h[3], l[3]);
    size_t base = (size_t)i * K3_HID + t * 4;
    __nv_bfloat162 hp0 = __halves2bfloat162(h[0], h[1]);
    __nv_bfloat162 hp1 = __halves2bfloat162(h[2], h[3]);
    __nv_bfloat162 lp0 = __halves2bfloat162(l[0], l[1]);
    __nv_bfloat162 lp1 = __halves2bfloat162(l[2], l[3]);
    ((__nv_bfloat162*)&g_A[base])[0] = hp0;
    ((__nv_bfloat162*)&g_A[base])[1] = hp1;
    ((__nv_bfloat162*)&g_A[base + HID])[0] = hp0;
    ((__nv_bfloat162*)&g_A[base + HID])[1] = hp1;
    ((__nv_bfloat162*)&g_A[base + 2 * HID])[0] = lp0;
    ((__nv_bfloat162*)&g_A[base + 2 * HID])[1] = lp1;
}

// ---------------------------------------------------------------------------
// bf16 HMMA GEMM: C[M x 512] = A'[M x Ktot] * B'[512 x Ktot]^T + bias (+relu)
// BM=128 BN=128 BK=32, 256 thr, warp grid 2x4 (warp tile 64x32), cp.async
// double buffer, ldmatrix fragments, pad-40 rows (80B) -> conflict-free.
// ---------------------------------------------------------------------------
#define BM 128
#define BN 128
#define BK 32
#define GTHR 256
#define RPAD 40   // bf16 per smem row
#define ROWB 80   // bytes per smem row

__global__ __launch_bounds__(GTHR, 2)
void gemm_hmma_kernel(const __nv_bfloat16* __restrict__ A, int lda,
                      const __nv_bfloat16* __restrict__ B, int ldb,
                      const float* __restrict__ bias,
                      float* __restrict__ C, int Ktot, int relu) {
    __shared__ __align__(16) __nv_bfloat16 As[2][BM * RPAD];
    __shared__ __align__(16) __nv_bfloat16 Bs[2][BN * RPAD];

    const int tid = threadIdx.x;
    const int lane = tid & 31;
    const int wid = tid >> 5;
    const int warp_m = wid >> 2;  // 0..1
    const int warp_n = wid & 3;   // 0..3
    const int m0 = blockIdx.y * BM;
    const int n0 = blockIdx.x * BN;

    uint32_t sA[2], sB[2];
    sA[0] = smem_to_u32(&As[0][0]);
    sA[1] = smem_to_u32(&As[1][0]);
    sB[0] = smem_to_u32(&Bs[0][0]);
    sB[1] = smem_to_u32(&Bs[1][0]);

    float acc[4][4][4];
#pragma unroll
    for (int i = 0; i < 4; i++)
#pragma unroll
        for (int j = 0; j < 4; j++)
#pragma unroll
            for (int q = 0; q < 4; q++) acc[i][j][q] = 0.0f;

    const int KT = Ktot / BK;

    // ldmatrix per-lane geometry
    const int mat = lane >> 3;       // matrix index 0..3
    const int mrow = lane & 7;       // row within 8x8 matrix
    // A: m0..m3 = (r+0,k0),(r+8,k0),(r+0,k8),(r+8,k8)
    const int a_row = warp_m * 64 + ((mat & 1) << 3) + mrow;
    const int a_koff = (mat >> 1) << 3;
    // B: m0..m3 = (n+0,k0),(n+0,k8),(n+8,k0),(n+8,k8)
    const int b_row = warp_n * 32 + ((mat >> 1) << 3) + mrow;
    const int b_koff = (mat & 1) << 3;

#define LOAD_STAGE(kt, buf)                                                      \
    do {                                                                         \
        const int kk_ = (kt) * BK;                                               \
        for (int c = tid; c < BM * 4; c += GTHR) {                               \
            int r_ = c >> 2, cc_ = c & 3;                                        \
            cp_async16(sA[buf] + r_ * ROWB + cc_ * 16,                           \
                       A + (size_t)(m0 + r_) * lda + kk_ + cc_ * 8);             \
        }                                                                        \
        for (int c = tid; c < BN * 4; c += GTHR) {                               \
            int r_ = c >> 2, cc_ = c & 3;                                        \
            cp_async16(sB[buf] + r_ * ROWB + cc_ * 16,                           \
                       B + (size_t)(n0 + r_) * ldb + kk_ + cc_ * 8);             \
        }                                                                        \
    } while (0)

    LOAD_STAGE(0, 0);
    CP_COMMIT();

    for (int kt = 0; kt < KT; kt++) {
        const int buf = kt & 1;
        if (kt + 1 < KT) {
            LOAD_STAGE(kt + 1, buf ^ 1);
            CP_COMMIT();
            CP_WAIT1();
        } else {
            CP_WAIT0();
        }
        __syncthreads();

#pragma unroll
        for (int ks = 0; ks < 2; ks++) {
            uint32_t af[4][4];
#pragma unroll
            for (int mt = 0; mt < 4; mt++) {
                uint32_t addr = sA[buf] + (a_row + mt * 16) * ROWB +
                                (ks * 16 + a_koff) * 2;
                ldsm_x4(af[mt][0], af[mt][1], af[mt][2], af[mt][3], addr);
            }
            uint32_t bfr[4][2];
#pragma unroll
            for (int p = 0; p < 2; p++) {
                uint32_t r0, r1, r2, r3;
                uint32_t addr = sB[buf] + (b_row + p * 16) * ROWB +
                                (ks * 16 + b_koff) * 2;
                ldsm_x4(r0, r1, r2, r3, addr);
                bfr[2 * p][0] = r0; bfr[2 * p][1] = r1;
                bfr[2 * p + 1][0] = r2; bfr[2 * p + 1][1] = r3;
            }
#pragma unroll
            for (int mt = 0; mt < 4; mt++)
#pragma unroll
                for (int nt = 0; nt < 4; nt++)
                    mma16816(acc[mt][nt], af[mt], bfr[nt]);
        }
        __syncthreads();
    }

    // epilogue
#pragma unroll
    for (int mt = 0; mt < 4; mt++) {
        const int rm = m0 + warp_m * 64 + mt * 16 + (lane >> 2);
#pragma unroll
        for (int nt = 0; nt < 4; nt++) {
            const int cn = n0 + warp_n * 32 + nt * 8 + ((lane & 3) << 1);
            const float b0 = bias[cn], b1 = bias[cn + 1];
            float2 v0, v1;
            v0.x = acc[mt][nt][0] + b0;
            v0.y = acc[mt][nt][1] + b1;
            v1.x = acc[mt][nt][2] + b0;
            v1.y = acc[mt][nt][3] + b1;
            if (relu) {
                v0.x = fmaxf(v0.x, 0.0f); v0.y = fmaxf(v0.y, 0.0f);
                v1.x = fmaxf(v1.x, 0.0f); v1.y = fmaxf(v1.y, 0.0f);
            }
            *(float2*)&C[(size_t)rm * HID + cn] = v0;
            *(float2*)&C[(size_t)(rm + 8) * HID + cn] = v1;
        }
    }
}

// ---------------------------------------------------------------------------
extern "C" void kernel_launch(void* const* d_in, const int* in_sizes, int n_in,
                              void* d_out, int out_size) {
    const float* node_in = (const float*)d_in[0];
    const int*   edges   = (const int*)d_in[1];
    const float* W_emb   = (const float*)d_in[2];
    const float* b_emb   = (const float*)d_in[3];
    const float* W1      = (const float*)d_in[4];
    const float* b1      = (const float*)d_in[5];
    const float* W2      = (const float*)d_in[6];
    const float* b2      = (const float*)d_in[7];
    const float* W3      = (const float*)d_in[8];
    const float* b3      = (const float*)d_in[9];
    float* out = (float*)d_out;

    __nv_bfloat16* A; cudaGetSymbolAddress((void**)&A, g_A);
    __nv_bfloat16* W; cudaGetSymbolAddress((void**)&W, g_W);
    float* X; cudaGetSymbolAddress((void**)&X, g_X);

    deg_kernel<<<(N_NODES + 255) / 256, 256>>>(edges);
    convert_in_kernel<<<512, 256>>>(node_in);
    wsplit_kernel<<<256, 256>>>(W_emb, F_NODE, HID, W + WOFF_E);
    wsplit_kernel<<<512, 256>>>(W1, HID, HID, W + WOFF_1);
    wsplit_kernel<<<512, 256>>>(W2, HID, HID, W + WOFF_2);
    wsplit_kernel<<<512, 256>>>(W3, HID, HID, W + WOFF_3);

    dim3 gg(HID / BN, N_NODES / BM);  // (4, 64)

    // embed
    gemm_hmma_kernel<<<gg, GTHR>>>(A, K3_EMB, W + WOFF_E, K3_EMB, b_emb, X,
                                   K3_EMB, 0);
    // layer 1
    spmm_kernel<<<N_NODES, 128>>>(edges, X);
    gemm_hmma_kernel<<<gg, GTHR>>>(A, K3_HID, W + WOFF_1, K3_HID, b1, X,
                                   K3_HID, 1);
    // layer 2
    spmm_kernel<<<N_NODES, 128>>>(edges, X);
    gemm_hmma_kernel<<<gg, GTHR>>>(A, K3_HID, W + WOFF_2, K3_HID, b2, X,
                                   K3_HID, 1);
    // layer 3 -> out
    spmm_kernel<<<N_NODES, 128>>>(edges, X);
    gemm_hmma_kernel<<<gg, GTHR>>>(A, K3_HID, W + WOFF_3, K3_HID, b3, out,
                                   K3_HID, 0);
}

// round 5
// speedup vs baseline: 1.8853x; 1.0356x over previous
#include <cuda_runtime.h>
#include <cuda_bf16.h>
#include <cstdint>

#define N_NODES 8192
#define M_NBR   16
#define F_NODE  128
#define HID     512

// K-split-3 layout: A' = [Ah | Ah | Al], B' = [Bh | Bl | Bh] along K.
#define K3_HID  (3 * HID)     // 1536
#define K3_EMB  (3 * F_NODE)  // 384

// ---------------- scratch (__device__ globals; no allocations) ----------------
__device__ __nv_bfloat16 g_A[N_NODES * K3_HID];
__device__ float         g_X[N_NODES * HID];
__device__ float         g_dinv[N_NODES];
#define WOFF_1 0
#define WOFF_2 (HID * K3_HID)
#define WOFF_3 (2 * HID * K3_HID)
#define WOFF_E (3 * HID * K3_HID)
__device__ __nv_bfloat16 g_W[3 * HID * K3_HID + HID * K3_EMB];

// ---------------- PTX helpers (compute_103-safe: no tcgen05) ----------------
__device__ __forceinline__ uint32_t smem_to_u32(const void* p) {
    uint32_t a;
    asm("{ .reg .u64 t; cvta.to.shared.u64 t, %1; cvt.u32.u64 %0, t; }" : "=r"(a) : "l"(p));
    return a;
}
__device__ __forceinline__ void cp_async16(uint32_t saddr, const void* gptr) {
    asm volatile("cp.async.cg.shared.global [%0], [%1], 16;" :: "r"(saddr), "l"(gptr));
}
#define CP_COMMIT() asm volatile("cp.async.commit_group;" ::: "memory")
#define CP_WAIT0()  asm volatile("cp.async.wait_group 0;" ::: "memory")
#define CP_WAIT1()  asm volatile("cp.async.wait_group 1;" ::: "memory")

__device__ __forceinline__ void ldsm_x4(uint32_t& r0, uint32_t& r1, uint32_t& r2,
                                        uint32_t& r3, uint32_t addr) {
    asm volatile("ldmatrix.sync.aligned.m8n8.x4.shared.b16 {%0,%1,%2,%3}, [%4];"
                 : "=r"(r0), "=r"(r1), "=r"(r2), "=r"(r3) : "r"(addr));
}
__device__ __forceinline__ void mma16816(float* d, const uint32_t* a, const uint32_t* b) {
    asm volatile(
        "mma.sync.aligned.m16n8k16.row.col.f32.bf16.bf16.f32 "
        "{%0,%1,%2,%3}, {%4,%5,%6,%7}, {%8,%9}, {%0,%1,%2,%3};"
        : "+f"(d[0]), "+f"(d[1]), "+f"(d[2]), "+f"(d[3])
        : "r"(a[0]), "r"(a[1]), "r"(a[2]), "r"(a[3]), "r"(b[0]), "r"(b[1]));
}

__device__ __forceinline__ void split_bf16(float v, __nv_bfloat16& h, __nv_bfloat16& l) {
    h = __float2bfloat16(v);
    l = __float2bfloat16(v - __bfloat162float(h));
}

// ---------------------------------------------------------------------------
// dinv = (1 + #valid)^{-1/2}
// ---------------------------------------------------------------------------
__global__ void deg_kernel(const int* __restrict__ idx) {
    int i = blockIdx.x * blockDim.x + threadIdx.x;
    if (i >= N_NODES) return;
    int cnt = 1;
#pragma unroll
    for (int k = 0; k < M_NBR; k++) cnt += (idx[i * M_NBR + k] >= 0) ? 1 : 0;
    g_dinv[i] = rsqrtf((float)cnt);
}

// ---------------------------------------------------------------------------
// node_in (fp32, stride F_NODE) -> g_A split rows [hi | hi | lo], stride K3_EMB
// ---------------------------------------------------------------------------
__global__ void convert_in_kernel(const float* __restrict__ src) {
    int total = N_NODES * F_NODE;
    for (int i = blockIdx.x * blockDim.x + threadIdx.x; i < total;
         i += gridDim.x * blockDim.x) {
        int r = i / F_NODE, c = i % F_NODE;
        __nv_bfloat16 h, l;
        split_bf16(src[i], h, l);
        size_t base = (size_t)r * K3_EMB;
        g_A[base + c] = h;
        g_A[base + F_NODE + c] = h;
        g_A[base + 2 * F_NODE + c] = l;
    }
}

// ---------------------------------------------------------------------------
// Coalesced transpose+split: W[K][N] fp32 -> o[N][3K] bf16 rows [hi | lo | hi]
// 32x32 smem tile, block (32,8), grid (N/32, K/32).
// ---------------------------------------------------------------------------
__global__ __launch_bounds__(256) void wsplit_kernel(const float* __restrict__ W,
                                                     int K, int N,
                                                     __nv_bfloat16* __restrict__ o) {
    __shared__ float tile[32][33];
    const int n0 = blockIdx.x * 32;
    const int k0 = blockIdx.y * 32;
    const int tx = threadIdx.x;   // 0..31
    const int ty = threadIdx.y;   // 0..7

#pragma unroll
    for (int r = 0; r < 4; r++) {
        int k = k0 + ty + r * 8;
        tile[ty + r * 8][tx] = W[(size_t)k * N + n0 + tx];
    }
    __syncthreads();

#pragma unroll
    for (int r = 0; r < 4; r++) {
        int n = ty + r * 8;                 // local row (N dim)
        float v = tile[tx][n];              // W[k0+tx][n0+n]
        __nv_bfloat16 h, l;
        split_bf16(v, h, l);
        size_t base = (size_t)(n0 + n) * (3 * K) + k0 + tx;
        o[base] = h;
        o[base + K] = l;
        o[base + 2 * K] = h;
    }
}

// ---------------------------------------------------------------------------
// SpMM: fp32 in (g_X), writes split bf16 rows [hi | hi | lo] stride K3_HID
// ---------------------------------------------------------------------------
__global__ __launch_bounds__(128) void spmm_kernel(const int* __restrict__ idx,
                                                   const float* __restrict__ X) {
    const int i = blockIdx.x;
    const int t = threadIdx.x;

    __shared__ int s_j[M_NBR];
    __shared__ float s_dj[M_NBR];
    if (t < M_NBR) {
        int j = idx[i * M_NBR + t];
        s_j[t] = j;
        s_dj[t] = (j >= 0) ? g_dinv[j] : 0.0f;
    }
    __syncthreads();

    const float di = g_dinv[i];
    float4 v = ((const float4*)&X[(size_t)i * HID])[t];
    float4 acc = make_float4(v.x * di, v.y * di, v.z * di, v.w * di);

#pragma unroll
    for (int k = 0; k < M_NBR; k++) {
        int j = s_j[k];
        if (j < 0) continue;
        float dj = s_dj[k];
        float4 w = ((const float4*)&X[(size_t)j * HID])[t];
        acc.x += dj * w.x;
        acc.y += dj * w.y;
        acc.z += dj * w.z;
        acc.w += dj * w.w;
    }
    acc.x *= di; acc.y *= di; acc.z *= di; acc.w *= di;

    __nv_bfloat16 h[4], l[4];
    split_bf16(acc.x, h[0], l[0]);
    split_bf16(acc.y, h[1], l[1]);
    split_bf16(acc.z, h[2], l[2]);
    split_bf16(acc.w, h[3], l[3]);
    size_t base = (size_t)i * K3_HID + t * 4;
    __nv_bfloat162 hp0 = __halves2bfloat162(h[0], h[1]);
    __nv_bfloat162 hp1 = __halves2bfloat162(h[2], h[3]);
    __nv_bfloat162 lp0 = __halves2bfloat162(l[0], l[1]);
    __nv_bfloat162 lp1 = __halves2bfloat162(l[2], l[3]);
    ((__nv_bfloat162*)&g_A[base])[0] = hp0;
    ((__nv_bfloat162*)&g_A[base])[1] = hp1;
    ((__nv_bfloat162*)&g_A[base + HID])[0] = hp0;
    ((__nv_bfloat162*)&g_A[base + HID])[1] = hp1;
    ((__nv_bfloat162*)&g_A[base + 2 * HID])[0] = lp0;
    ((__nv_bfloat162*)&g_A[base + 2 * HID])[1] = lp1;
}

// ---------------------------------------------------------------------------
// bf16 HMMA GEMM, 3-stage cp.async pipeline, compile-time Ktot.
// BM=128 BN=128 BK=32, 256 thr, warp grid 2x4 (warp tile 64x32), pad-40 rows.
// ---------------------------------------------------------------------------
#define BM 128
#define BN 128
#define BK 32
#define GTHR 256
#define RPAD 40          // bf16 per smem row
#define ROWB 80          // bytes per smem row
#define STAGE_B (2 * BM * RPAD * 2)        // As+Bs per stage = 20480 B
#define GSMEM   (3 * STAGE_B)              // 61440 B dynamic

template <int Ktot>
__global__ __launch_bounds__(GTHR, 2)
void gemm_hmma_kernel(const __nv_bfloat16* __restrict__ A,
                      const __nv_bfloat16* __restrict__ B,
                      const float* __restrict__ bias,
                      float* __restrict__ C, int relu) {
    extern __shared__ __align__(16) char dynsmem[];

    const int tid = threadIdx.x;
    const int lane = tid & 31;
    const int wid = tid >> 5;
    const int warp_m = wid >> 2;  // 0..1
    const int warp_n = wid & 3;   // 0..3
    const int m0 = blockIdx.y * BM;
    const int n0 = blockIdx.x * BN;

    uint32_t sA[3], sB[3];
#pragma unroll
    for (int s = 0; s < 3; s++) {
        sA[s] = smem_to_u32(dynsmem + s * STAGE_B);
        sB[s] = sA[s] + BM * ROWB;
    }

    float acc[4][4][4];
#pragma unroll
    for (int i = 0; i < 4; i++)
#pragma unroll
        for (int j = 0; j < 4; j++)
#pragma unroll
            for (int q = 0; q < 4; q++) acc[i][j][q] = 0.0f;

    constexpr int KT = Ktot / BK;

    const int mat = lane >> 3;
    const int mrow = lane & 7;
    const int a_row = warp_m * 64 + ((mat & 1) << 3) + mrow;
    const int a_koff = (mat >> 1) << 3;
    const int b_row = warp_n * 32 + ((mat >> 1) << 3) + mrow;
    const int b_koff = (mat & 1) << 3;

    // per-thread load slots: 256 thr cover BM*4 (=512) A chunks in 2 steps
    const int lr = tid >> 2;        // 0..63
    const int lc = tid & 3;         // 0..3

#define LOAD_STAGE(kt, buf)                                                     \
    do {                                                                        \
        const int kk_ = (kt) * BK;                                              \
        cp_async16(sA[buf] + lr * ROWB + lc * 16,                               \
                   A + (size_t)(m0 + lr) * Ktot + kk_ + lc * 8);                \
        cp_async16(sA[buf] + (lr + 64) * ROWB + lc * 16,                        \
                   A + (size_t)(m0 + lr + 64) * Ktot + kk_ + lc * 8);           \
        cp_async16(sB[buf] + lr * ROWB + lc * 16,                               \
                   B + (size_t)(n0 + lr) * Ktot + kk_ + lc * 8);                \
        cp_async16(sB[buf] + (lr + 64) * ROWB + lc * 16,                        \
                   B + (size_t)(n0 + lr + 64) * Ktot + kk_ + lc * 8);           \
    } while (0)

    LOAD_STAGE(0, 0);
    CP_COMMIT();
    LOAD_STAGE(1, 1);
    CP_COMMIT();

    for (int kt = 0; kt < KT; kt++) {
        const int buf = kt % 3;
        if (kt + 1 < KT) CP_WAIT1(); else CP_WAIT0();
        __syncthreads();
        if (kt + 2 < KT) {
            LOAD_STAGE(kt + 2, (kt + 2) % 3);
            CP_COMMIT();
        }

#pragma unroll
        for (int ks = 0; ks < 2; ks++) {
            uint32_t af[4][4];
#pragma unroll
            for (int mt = 0; mt < 4; mt++) {
                uint32_t addr = sA[buf] + (a_row + mt * 16) * ROWB +
                                (ks * 16 + a_koff) * 2;
                ldsm_x4(af[mt][0], af[mt][1], af[mt][2], af[mt][3], addr);
            }
            uint32_t bfr[4][2];
#pragma unroll
            for (int p = 0; p < 2; p++) {
                uint32_t r0, r1, r2, r3;
                uint32_t addr = sB[buf] + (b_row + p * 16) * ROWB +
                                (ks * 16 + b_koff) * 2;
                ldsm_x4(r0, r1, r2, r3, addr);
                bfr[2 * p][0] = r0; bfr[2 * p][1] = r1;
                bfr[2 * p + 1][0] = r2; bfr[2 * p + 1][1] = r3;
            }
#pragma unroll
            for (int mt = 0; mt < 4; mt++)
#pragma unroll
                for (int nt = 0; nt < 4; nt++)
                    mma16816(acc[mt][nt], af[mt], bfr[nt]);
        }
        __syncthreads();
    }

    // epilogue
#pragma unroll
    for (int mt = 0; mt < 4; mt++) {
        const int rm = m0 + warp_m * 64 + mt * 16 + (lane >> 2);
#pragma unroll
        for (int nt = 0; nt < 4; nt++) {
            const int cn = n0 + warp_n * 32 + nt * 8 + ((lane & 3) << 1);
            const float b0 = bias[cn], b1 = bias[cn + 1];
            float2 v0, v1;
            v0.x = acc[mt][nt][0] + b0;
            v0.y = acc[mt][nt][1] + b1;
            v1.x = acc[mt][nt][2] + b0;
            v1.y = acc[mt][nt][3] + b1;
            if (relu) {
                v0.x = fmaxf(v0.x, 0.0f); v0.y = fmaxf(v0.y, 0.0f);
                v1.x = fmaxf(v1.x, 0.0f); v1.y = fmaxf(v1.y, 0.0f);
            }
            *(float2*)&C[(size_t)rm * HID + cn] = v0;
            *(float2*)&C[(size_t)(rm + 8) * HID + cn] = v1;
        }
    }
}

// ---------------------------------------------------------------------------
extern "C" void kernel_launch(void* const* d_in, const int* in_sizes, int n_in,
                              void* d_out, int out_size) {
    const float* node_in = (const float*)d_in[0];
    const int*   edges   = (const int*)d_in[1];
    const float* W_emb   = (const float*)d_in[2];
    const float* b_emb   = (const float*)d_in[3];
    const float* W1      = (const float*)d_in[4];
    const float* b1      = (const float*)d_in[5];
    const float* W2      = (const float*)d_in[6];
    const float* b2      = (const float*)d_in[7];
    const float* W3      = (const float*)d_in[8];
    const float* b3      = (const float*)d_in[9];
    float* out = (float*)d_out;

    __nv_bfloat16* A; cudaGetSymbolAddress((void**)&A, g_A);
    __nv_bfloat16* W; cudaGetSymbolAddress((void**)&W, g_W);
    float* X; cudaGetSymbolAddress((void**)&X, g_X);

    cudaFuncSetAttribute(gemm_hmma_kernel<K3_HID>,
                         cudaFuncAttributeMaxDynamicSharedMemorySize, GSMEM);
    cudaFuncSetAttribute(gemm_hmma_kernel<K3_EMB>,
                         cudaFuncAttributeMaxDynamicSharedMemorySize, GSMEM);

    deg_kernel<<<(N_NODES + 255) / 256, 256>>>(edges);
    convert_in_kernel<<<512, 256>>>(node_in);
    {
        dim3 tb(32, 8);
        wsplit_kernel<<<dim3(HID / 32, F_NODE / 32), tb>>>(W_emb, F_NODE, HID, W + WOFF_E);
        wsplit_kernel<<<dim3(HID / 32, HID / 32), tb>>>(W1, HID, HID, W + WOFF_1);
        wsplit_kernel<<<dim3(HID / 32, HID / 32), tb>>>(W2, HID, HID, W + WOFF_2);
        wsplit_kernel<<<dim3(HID / 32, HID / 32), tb>>>(W3, HID, HID, W + WOFF_3);
    }

    dim3 gg(HID / BN, N_NODES / BM);  // (4, 64)

    // embed
    gemm_hmma_kernel<K3_EMB><<<gg, GTHR, GSMEM>>>(A, W + WOFF_E, b_emb, X, 0);
    // layer 1
    spmm_kernel<<<N_NODES, 128>>>(edges, X);
    gemm_hmma_kernel<K3_HID><<<gg, GTHR, GSMEM>>>(A, W + WOFF_1, b1, X, 1);
    // layer 2
    spmm_kernel<<<N_NODES, 128>>>(edges, X);
    gemm_hmma_kernel<K3_HID><<<gg, GTHR, GSMEM>>>(A, W + WOFF_2, b2, X, 1);
    // layer 3 -> out
    spmm_kernel<<<N_NODES, 128>>>(edges, X);
    gemm_hmma_kernel<K3_HID><<<gg, GTHR, GSMEM>>>(A, W + WOFF_3, b3, out, 0);
}

// round 6
// speedup vs baseline: 2.4907x; 1.3211x over previous
#include <cuda_runtime.h>
#include <cuda_fp16.h>
#include <cstdint>

#define N_NODES 8192
#define M_NBR   16
#define F_NODE  128
#define HID     512

// 2-term fp16 split: A' = [Ah | Al] (stride 2K), B single fp16 used twice.
#define K2_HID  (2 * HID)     // 1024
#define K2_EMB  (2 * F_NODE)  // 256

// ---------------- scratch (__device__ globals; no allocations) ----------------
__device__ __half g_A[N_NODES * K2_HID];
__device__ float  g_X[N_NODES * HID];
__device__ float  g_dinv[N_NODES];
#define WOFF_1 0
#define WOFF_2 (HID * HID)
#define WOFF_3 (2 * HID * HID)
#define WOFF_E (3 * HID * HID)
__device__ __half g_W[3 * HID * HID + HID * F_NODE];

// ---------------- PTX helpers (compute_103-safe) ----------------
__device__ __forceinline__ uint32_t smem_to_u32(const void* p) {
    uint32_t a;
    asm("{ .reg .u64 t; cvta.to.shared.u64 t, %1; cvt.u32.u64 %0, t; }" : "=r"(a) : "l"(p));
    return a;
}
__device__ __forceinline__ void cp_async16(uint32_t saddr, const void* gptr) {
    asm volatile("cp.async.cg.shared.global [%0], [%1], 16;" :: "r"(saddr), "l"(gptr));
}
#define CP_COMMIT() asm volatile("cp.async.commit_group;" ::: "memory")
#define CP_WAIT0()  asm volatile("cp.async.wait_group 0;" ::: "memory")
#define CP_WAIT1()  asm volatile("cp.async.wait_group 1;" ::: "memory")

__device__ __forceinline__ void ldsm_x4(uint32_t& r0, uint32_t& r1, uint32_t& r2,
                                        uint32_t& r3, uint32_t addr) {
    asm volatile("ldmatrix.sync.aligned.m8n8.x4.shared.b16 {%0,%1,%2,%3}, [%4];"
                 : "=r"(r0), "=r"(r1), "=r"(r2), "=r"(r3) : "r"(addr));
}
__device__ __forceinline__ void mma16816(float* d, const uint32_t* a, const uint32_t* b) {
    asm volatile(
        "mma.sync.aligned.m16n8k16.row.col.f32.f16.f16.f32 "
        "{%0,%1,%2,%3}, {%4,%5,%6,%7}, {%8,%9}, {%0,%1,%2,%3};"
        : "+f"(d[0]), "+f"(d[1]), "+f"(d[2]), "+f"(d[3])
        : "r"(a[0]), "r"(a[1]), "r"(a[2]), "r"(a[3]), "r"(b[0]), "r"(b[1]));
}

__device__ __forceinline__ void split_fp16(float v, __half& h, __half& l) {
    h = __float2half_rn(v);
    l = __float2half_rn(v - __half2float(h));
}

// ---------------------------------------------------------------------------
// dinv = (1 + #valid)^{-1/2}
// ---------------------------------------------------------------------------
__global__ void deg_kernel(const int* __restrict__ idx) {
    int i = blockIdx.x * blockDim.x + threadIdx.x;
    if (i >= N_NODES) return;
    int cnt = 1;
#pragma unroll
    for (int k = 0; k < M_NBR; k++) cnt += (idx[i * M_NBR + k] >= 0) ? 1 : 0;
    g_dinv[i] = rsqrtf((float)cnt);
}

// ---------------------------------------------------------------------------
// node_in (fp32, stride F_NODE) -> g_A rows [hi | lo], stride K2_EMB
// ---------------------------------------------------------------------------
__global__ void convert_in_kernel(const float* __restrict__ src) {
    int total = N_NODES * F_NODE;
    for (int i = blockIdx.x * blockDim.x + threadIdx.x; i < total;
         i += gridDim.x * blockDim.x) {
        int r = i / F_NODE, c = i % F_NODE;
        __half h, l;
        split_fp16(src[i], h, l);
        size_t base = (size_t)r * K2_EMB;
        g_A[base + c] = h;
        g_A[base + F_NODE + c] = l;
    }
}

// ---------------------------------------------------------------------------
// Coalesced transpose: W[K][N] fp32 -> o[N][K] fp16
// ---------------------------------------------------------------------------
__global__ __launch_bounds__(256) void wconv_kernel(const float* __restrict__ W,
                                                    int K, int N,
                                                    __half* __restrict__ o) {
    __shared__ float tile[32][33];
    const int n0 = blockIdx.x * 32;
    const int k0 = blockIdx.y * 32;
    const int tx = threadIdx.x;   // 0..31
    const int ty = threadIdx.y;   // 0..7

#pragma unroll
    for (int r = 0; r < 4; r++) {
        int k = k0 + ty + r * 8;
        tile[ty + r * 8][tx] = W[(size_t)k * N + n0 + tx];
    }
    __syncthreads();

#pragma unroll
    for (int r = 0; r < 4; r++) {
        int n = ty + r * 8;
        float v = tile[tx][n];   // W[k0+tx][n0+n]
        o[(size_t)(n0 + n) * K + k0 + tx] = __float2half_rn(v);
    }
}

// ---------------------------------------------------------------------------
// SpMM: fp32 in (g_X), writes fp16 split rows [hi | lo] stride K2_HID
// ---------------------------------------------------------------------------
__global__ __launch_bounds__(128) void spmm_kernel(const int* __restrict__ idx,
                                                   const float* __restrict__ X) {
    const int i = blockIdx.x;
    const int t = threadIdx.x;

    __shared__ int s_j[M_NBR];
    __shared__ float s_dj[M_NBR];
    if (t < M_NBR) {
        int j = idx[i * M_NBR + t];
        s_j[t] = j;
        s_dj[t] = (j >= 0) ? g_dinv[j] : 0.0f;
    }
    __syncthreads();

    const float di = g_dinv[i];
    float4 v = ((const float4*)&X[(size_t)i * HID])[t];
    float4 acc = make_float4(v.x * di, v.y * di, v.z * di, v.w * di);

#pragma unroll
    for (int k = 0; k < M_NBR; k++) {
        int j = s_j[k];
        if (j < 0) continue;
        float dj = s_dj[k];
        float4 w = ((const float4*)&X[(size_t)j * HID])[t];
        acc.x += dj * w.x;
        acc.y += dj * w.y;
        acc.z += dj * w.z;
        acc.w += dj * w.w;
    }
    acc.x *= di; acc.y *= di; acc.z *= di; acc.w *= di;

    __half h[4], l[4];
    split_fp16(acc.x, h[0], l[0]);
    split_fp16(acc.y, h[1], l[1]);
    split_fp16(acc.z, h[2], l[2]);
    split_fp16(acc.w, h[3], l[3]);
    size_t base = (size_t)i * K2_HID + t * 4;
    ((__half2*)&g_A[base])[0] = __halves2half2(h[0], h[1]);
    ((__half2*)&g_A[base])[1] = __halves2half2(h[2], h[3]);
    ((__half2*)&g_A[base + HID])[0] = __halves2half2(l[0], l[1]);
    ((__half2*)&g_A[base + HID])[1] = __halves2half2(l[2], l[3]);
}

// ---------------------------------------------------------------------------
// fp16 HMMA GEMM: C[M x 512] = A'[M x 2K] * [B|B]^T + bias (+relu)
// A row stride 2K; B row stride K, K-index wraps at K.
// BM=128 BN=128 BK=32, 256 thr, warp grid 2x4, 3-stage cp.async, pad-40 rows.
// ---------------------------------------------------------------------------
#define BM 128
#define BN 128
#define BK 32
#define GTHR 256
#define RPAD 40
#define ROWB 80
#define STAGE_B (2 * BM * RPAD * 2)   // 20480 B per stage (As+Bs)
#define GSMEM   (3 * STAGE_B)         // 61440 B

template <int K>
__global__ __launch_bounds__(GTHR, 2)
void gemm_hmma_kernel(const __half* __restrict__ A,
                      const __half* __restrict__ B,
                      const float* __restrict__ bias,
                      float* __restrict__ C, int relu) {
    extern __shared__ __align__(16) char dynsmem[];

    const int tid = threadIdx.x;
    const int lane = tid & 31;
    const int wid = tid >> 5;
    const int warp_m = wid >> 2;
    const int warp_n = wid & 3;
    const int m0 = blockIdx.y * BM;
    const int n0 = blockIdx.x * BN;

    uint32_t sA[3], sB[3];
#pragma unroll
    for (int s = 0; s < 3; s++) {
        sA[s] = smem_to_u32(dynsmem + s * STAGE_B);
        sB[s] = sA[s] + BM * ROWB;
    }

    float acc[4][4][4];
#pragma unroll
    for (int i = 0; i < 4; i++)
#pragma unroll
        for (int j = 0; j < 4; j++)
#pragma unroll
            for (int q = 0; q < 4; q++) acc[i][j][q] = 0.0f;

    constexpr int KT = (2 * K) / BK;      // total K' tiles
    constexpr int lda = 2 * K;

    const int mat = lane >> 3;
    const int mrow = lane & 7;
    const int a_row = warp_m * 64 + ((mat & 1) << 3) + mrow;
    const int a_koff = (mat >> 1) << 3;
    const int b_row = warp_n * 32 + ((mat >> 1) << 3) + mrow;
    const int b_koff = (mat & 1) << 3;

    const int lr = tid >> 2;   // 0..63
    const int lc = tid & 3;    // 0..3

#define LOAD_STAGE(kt, buf)                                                     \
    do {                                                                        \
        const int kk_ = (kt) * BK;                                              \
        const int kb_ = (kk_ < K) ? kk_ : kk_ - K;                              \
        cp_async16(sA[buf] + lr * ROWB + lc * 16,                               \
                   A + (size_t)(m0 + lr) * lda + kk_ + lc * 8);                 \
        cp_async16(sA[buf] + (lr + 64) * ROWB + lc * 16,                        \
                   A + (size_t)(m0 + lr + 64) * lda + kk_ + lc * 8);            \
        cp_async16(sB[buf] + lr * ROWB + lc * 16,                               \
                   B + (size_t)(n0 + lr) * K + kb_ + lc * 8);                   \
        cp_async16(sB[buf] + (lr + 64) * ROWB + lc * 16,                        \
                   B + (size_t)(n0 + lr + 64) * K + kb_ + lc * 8);              \
    } while (0)

    LOAD_STAGE(0, 0);
    CP_COMMIT();
    LOAD_STAGE(1, 1);
    CP_COMMIT();

    for (int kt = 0; kt < KT; kt++) {
        const int buf = kt % 3;
        if (kt + 1 < KT) CP_WAIT1(); else CP_WAIT0();
        __syncthreads();
        if (kt + 2 < KT) {
            LOAD_STAGE(kt + 2, (kt + 2) % 3);
            CP_COMMIT();
        }

#pragma unroll
        for (int ks = 0; ks < 2; ks++) {
            uint32_t af[4][4];
#pragma unroll
            for (int mt = 0; mt < 4; mt++) {
                uint32_t addr = sA[buf] + (a_row + mt * 16) * ROWB +
                                (ks * 16 + a_koff) * 2;
                ldsm_x4(af[mt][0], af[mt][1], af[mt][2], af[mt][3], addr);
            }
            uint32_t bfr[4][2];
#pragma unroll
            for (int p = 0; p < 2; p++) {
                uint32_t r0, r1, r2, r3;
                uint32_t addr = sB[buf] + (b_row + p * 16) * ROWB +
                                (ks * 16 + b_koff) * 2;
                ldsm_x4(r0, r1, r2, r3, addr);
                bfr[2 * p][0] = r0; bfr[2 * p][1] = r1;
                bfr[2 * p + 1][0] = r2; bfr[2 * p + 1][1] = r3;
            }
#pragma unroll
            for (int mt = 0; mt < 4; mt++)
#pragma unroll
                for (int nt = 0; nt < 4; nt++)
                    mma16816(acc[mt][nt], af[mt], bfr[nt]);
        }
        __syncthreads();
    }

    // epilogue
#pragma unroll
    for (int mt = 0; mt < 4; mt++) {
        const int rm = m0 + warp_m * 64 + mt * 16 + (lane >> 2);
#pragma unroll
        for (int nt = 0; nt < 4; nt++) {
            const int cn = n0 + warp_n * 32 + nt * 8 + ((lane & 3) << 1);
            const float b0 = bias[cn], b1 = bias[cn + 1];
            float2 v0, v1;
            v0.x = acc[mt][nt][0] + b0;
            v0.y = acc[mt][nt][1] + b1;
            v1.x = acc[mt][nt][2] + b0;
            v1.y = acc[mt][nt][3] + b1;
            if (relu) {
                v0.x = fmaxf(v0.x, 0.0f); v0.y = fmaxf(v0.y, 0.0f);
                v1.x = fmaxf(v1.x, 0.0f); v1.y = fmaxf(v1.y, 0.0f);
            }
            *(float2*)&C[(size_t)rm * HID + cn] = v0;
            *(float2*)&C[(size_t)(rm + 8) * HID + cn] = v1;
        }
    }
}

// ---------------------------------------------------------------------------
extern "C" void kernel_launch(void* const* d_in, const int* in_sizes, int n_in,
                              void* d_out, int out_size) {
    const float* node_in = (const float*)d_in[0];
    const int*   edges   = (const int*)d_in[1];
    const float* W_emb   = (const float*)d_in[2];
    const float* b_emb   = (const float*)d_in[3];
    const float* W1      = (const float*)d_in[4];
    const float* b1      = (const float*)d_in[5];
    const float* W2      = (const float*)d_in[6];
    const float* b2      = (const float*)d_in[7];
    const float* W3      = (const float*)d_in[8];
    const float* b3      = (const float*)d_in[9];
    float* out = (float*)d_out;

    __half* A; cudaGetSymbolAddress((void**)&A, g_A);
    __half* W; cudaGetSymbolAddress((void**)&W, g_W);
    float* X; cudaGetSymbolAddress((void**)&X, g_X);

    cudaFuncSetAttribute(gemm_hmma_kernel<HID>,
                         cudaFuncAttributeMaxDynamicSharedMemorySize, GSMEM);
    cudaFuncSetAttribute(gemm_hmma_kernel<F_NODE>,
                         cudaFuncAttributeMaxDynamicSharedMemorySize, GSMEM);

    deg_kernel<<<(N_NODES + 255) / 256, 256>>>(edges);
    convert_in_kernel<<<512, 256>>>(node_in);
    {
        dim3 tb(32, 8);
        wconv_kernel<<<dim3(HID / 32, F_NODE / 32), tb>>>(W_emb, F_NODE, HID, W + WOFF_E);
        wconv_kernel<<<dim3(HID / 32, HID / 32), tb>>>(W1, HID, HID, W + WOFF_1);
        wconv_kernel<<<dim3(HID / 32, HID / 32), tb>>>(W2, HID, HID, W + WOFF_2);
        wconv_kernel<<<dim3(HID / 32, HID / 32), tb>>>(W3, HID, HID, W + WOFF_3);
    }

    dim3 gg(HID / BN, N_NODES / BM);  // (4, 64)

    // embed
    gemm_hmma_kernel<F_NODE><<<gg, GTHR, GSMEM>>>(A, W + WOFF_E, b_emb, X, 0);
    // layer 1
    spmm_kernel<<<N_NODES, 128>>>(edges, X);
    gemm_hmma_kernel<HID><<<gg, GTHR, GSMEM>>>(A, W + WOFF_1, b1, X, 1);
    // layer 2
    spmm_kernel<<<N_NODES, 128>>>(edges, X);
    gemm_hmma_kernel<HID><<<gg, GTHR, GSMEM>>>(A, W + WOFF_2, b2, X, 1);
    // layer 3 -> out
    spmm_kernel<<<N_NODES, 128>>>(edges, X);
    gemm_hmma_kernel<HID><<<gg, GTHR, GSMEM>>>(A, W + WOFF_3, b3, out, 0);
}

// round 7
// speedup vs baseline: 4.3657x; 1.7528x over previous
#include <cuda_runtime.h>
#include <cuda_fp16.h>
#include <cstdint>

#define N_NODES 8192
#define M_NBR   16
#define F_NODE  128
#define HID     512

// ---------------- scratch (__device__ globals; no allocations) ----------------
__device__ __half g_HA[N_NODES * HID];   // activation ping
__device__ __half g_HB[N_NODES * HID];   // activation pong
__device__ float  g_dinv[N_NODES];
#define WOFF_1 0
#define WOFF_2 (HID * HID)
#define WOFF_3 (2 * HID * HID)
#define WOFF_E (3 * HID * HID)
__device__ __half g_W[3 * HID * HID + HID * F_NODE];

// ---------------- PTX helpers (compute_103-safe) ----------------
__device__ __forceinline__ uint32_t smem_to_u32(const void* p) {
    uint32_t a;
    asm("{ .reg .u64 t; cvta.to.shared.u64 t, %1; cvt.u32.u64 %0, t; }" : "=r"(a) : "l"(p));
    return a;
}
__device__ __forceinline__ void cp_async16(uint32_t saddr, const void* gptr) {
    asm volatile("cp.async.cg.shared.global [%0], [%1], 16;" :: "r"(saddr), "l"(gptr));
}
#define CP_COMMIT() asm volatile("cp.async.commit_group;" ::: "memory")
#define CP_WAIT0()  asm volatile("cp.async.wait_group 0;" ::: "memory")
#define CP_WAIT1()  asm volatile("cp.async.wait_group 1;" ::: "memory")

__device__ __forceinline__ void ldsm_x4(uint32_t& r0, uint32_t& r1, uint32_t& r2,
                                        uint32_t& r3, uint32_t addr) {
    asm volatile("ldmatrix.sync.aligned.m8n8.x4.shared.b16 {%0,%1,%2,%3}, [%4];"
                 : "=r"(r0), "=r"(r1), "=r"(r2), "=r"(r3) : "r"(addr));
}
__device__ __forceinline__ void mma16816(float* d, const uint32_t* a, const uint32_t* b) {
    asm volatile(
        "mma.sync.aligned.m16n8k16.row.col.f32.f16.f16.f32 "
        "{%0,%1,%2,%3}, {%4,%5,%6,%7}, {%8,%9}, {%0,%1,%2,%3};"
        : "+f"(d[0]), "+f"(d[1]), "+f"(d[2]), "+f"(d[3])
        : "r"(a[0]), "r"(a[1]), "r"(a[2]), "r"(a[3]), "r"(b[0]), "r"(b[1]));
}

// ---------------------------------------------------------------------------
// dinv = (1 + #valid)^{-1/2}
// ---------------------------------------------------------------------------
__global__ void deg_kernel(const int* __restrict__ idx) {
    int i = blockIdx.x * blockDim.x + threadIdx.x;
    if (i >= N_NODES) return;
    int cnt = 1;
#pragma unroll
    for (int k = 0; k < M_NBR; k++) cnt += (idx[i * M_NBR + k] >= 0) ? 1 : 0;
    g_dinv[i] = rsqrtf((float)cnt);
}

// ---------------------------------------------------------------------------
// node_in fp32 [N][128] -> g_HA fp16 [N][128]  (coalesced)
// ---------------------------------------------------------------------------
__global__ void convert_in_kernel(const float* __restrict__ src) {
    int total = N_NODES * F_NODE;
    for (int i = blockIdx.x * blockDim.x + threadIdx.x; i < total;
         i += gridDim.x * blockDim.x) {
        g_HA[i] = __float2half_rn(src[i]);
    }
}

// ---------------------------------------------------------------------------
// Coalesced transpose: W[K][N] fp32 -> o[N][K] fp16 (32x32 smem tile)
// Fused variant: blockIdx.z picks one of three 512x512 weights.
// ---------------------------------------------------------------------------
__device__ __forceinline__ void wconv_tile(const float* __restrict__ W, int K, int N,
                                           __half* __restrict__ o,
                                           int n0, int k0, int tx, int ty) {
    __shared__ float tile[32][33];
#pragma unroll
    for (int r = 0; r < 4; r++) {
        int k = k0 + ty + r * 8;
        tile[ty + r * 8][tx] = W[(size_t)k * N + n0 + tx];
    }
    __syncthreads();
#pragma unroll
    for (int r = 0; r < 4; r++) {
        int n = ty + r * 8;
        o[(size_t)(n0 + n) * K + k0 + tx] = __float2half_rn(tile[tx][n]);
    }
}

__global__ __launch_bounds__(256) void wconv3_kernel(const float* __restrict__ W1,
                                                     const float* __restrict__ W2,
                                                     const float* __restrict__ W3,
                                                     __half* __restrict__ o) {
    const float* W = (blockIdx.z == 0) ? W1 : (blockIdx.z == 1) ? W2 : W3;
    __half* out = o + (size_t)blockIdx.z * HID * HID;
    wconv_tile(W, HID, HID, out, blockIdx.x * 32, blockIdx.y * 32,
               threadIdx.x, threadIdx.y);
}

__global__ __launch_bounds__(256) void wconvE_kernel(const float* __restrict__ W,
                                                     __half* __restrict__ o) {
    wconv_tile(W, F_NODE, HID, o, blockIdx.x * 32, blockIdx.y * 32,
               threadIdx.x, threadIdx.y);
}

// ---------------------------------------------------------------------------
// SpMM (fp16 in, fp16 out, fp32 accumulate):
//   Y[i,:] = di * ( di*X[i,:] + sum_valid dj*X[j,:] )
// 128 threads/row, 4 halves (8B) per thread.
// ---------------------------------------------------------------------------
__global__ __launch_bounds__(128) void spmm_kernel(const int* __restrict__ idx,
                                                   const __half* __restrict__ Xin,
                                                   __half* __restrict__ Xout) {
    const int i = blockIdx.x;
    const int t = threadIdx.x;

    __shared__ int s_j[M_NBR];
    __shared__ float s_dj[M_NBR];
    if (t < M_NBR) {
        int j = idx[i * M_NBR + t];
        s_j[t] = j;
        s_dj[t] = (j >= 0) ? g_dinv[j] : 0.0f;
    }
    __syncthreads();

    const float di = g_dinv[i];
    uint2 raw = ((const uint2*)(Xin + (size_t)i * HID))[t];
    float2 a0 = __half22float2(*(__half2*)&raw.x);
    float2 a1 = __half22float2(*(__half2*)&raw.y);
    float acc0 = a0.x * di, acc1 = a0.y * di, acc2 = a1.x * di, acc3 = a1.y * di;

#pragma unroll
    for (int k = 0; k < M_NBR; k++) {
        int j = s_j[k];
        if (j < 0) continue;
        float dj = s_dj[k];
        uint2 w = ((const uint2*)(Xin + (size_t)j * HID))[t];
        float2 w0 = __half22float2(*(__half2*)&w.x);
        float2 w1 = __half22float2(*(__half2*)&w.y);
        acc0 += dj * w0.x;
        acc1 += dj * w0.y;
        acc2 += dj * w1.x;
        acc3 += dj * w1.y;
    }
    uint2 outw;
    *(__half2*)&outw.x = __floats2half2_rn(acc0 * di, acc1 * di);
    *(__half2*)&outw.y = __floats2half2_rn(acc2 * di, acc3 * di);
    ((uint2*)(Xout + (size_t)i * HID))[t] = outw;
}

// ---------------------------------------------------------------------------
// fp16 HMMA GEMM: C[M x 512] = A[M x K] * B[512 x K]^T + bias (+relu)
// Output fp16 (intermediate layers) or fp32 (final layer) via template.
// BM=128 BN=128 BK=32, 256 thr, warp grid 2x4, 3-stage cp.async, pad-40 rows.
// ---------------------------------------------------------------------------
#define BM 128
#define BN 128
#define BK 32
#define GTHR 256
#define RPAD 40
#define ROWB 80
#define STAGE_B (2 * BM * RPAD * 2)   // 20480 B per stage (As+Bs)
#define GSMEM   (3 * STAGE_B)         // 61440 B

template <int K, bool HALF_OUT>
__global__ __launch_bounds__(GTHR, 2)
void gemm_hmma_kernel(const __half* __restrict__ A,
                      const __half* __restrict__ B,
                      const float* __restrict__ bias,
                      void* __restrict__ Cout, int relu) {
    extern __shared__ __align__(16) char dynsmem[];

    const int tid = threadIdx.x;
    const int lane = tid & 31;
    const int wid = tid >> 5;
    const int warp_m = wid >> 2;
    const int warp_n = wid & 3;
    const int m0 = blockIdx.y * BM;
    const int n0 = blockIdx.x * BN;

    uint32_t sA[3], sB[3];
#pragma unroll
    for (int s = 0; s < 3; s++) {
        sA[s] = smem_to_u32(dynsmem + s * STAGE_B);
        sB[s] = sA[s] + BM * ROWB;
    }

    float acc[4][4][4];
#pragma unroll
    for (int i = 0; i < 4; i++)
#pragma unroll
        for (int j = 0; j < 4; j++)
#pragma unroll
            for (int q = 0; q < 4; q++) acc[i][j][q] = 0.0f;

    constexpr int KT = K / BK;

    const int mat = lane >> 3;
    const int mrow = lane & 7;
    const int a_row = warp_m * 64 + ((mat & 1) << 3) + mrow;
    const int a_koff = (mat >> 1) << 3;
    const int b_row = warp_n * 32 + ((mat >> 1) << 3) + mrow;
    const int b_koff = (mat & 1) << 3;

    const int lr = tid >> 2;   // 0..63
    const int lc = tid & 3;    // 0..3

#define LOAD_STAGE(kt, buf)                                                     \
    do {                                                                        \
        const int kk_ = (kt) * BK;                                              \
        cp_async16(sA[buf] + lr * ROWB + lc * 16,                               \
                   A + (size_t)(m0 + lr) * K + kk_ + lc * 8);                   \
        cp_async16(sA[buf] + (lr + 64) * ROWB + lc * 16,                        \
                   A + (size_t)(m0 + lr + 64) * K + kk_ + lc * 8);              \
        cp_async16(sB[buf] + lr * ROWB + lc * 16,                               \
                   B + (size_t)(n0 + lr) * K + kk_ + lc * 8);                   \
        cp_async16(sB[buf] + (lr + 64) * ROWB + lc * 16,                        \
                   B + (size_t)(n0 + lr + 64) * K + kk_ + lc * 8);              \
    } while (0)

    LOAD_STAGE(0, 0);
    CP_COMMIT();
    LOAD_STAGE(1, 1);
    CP_COMMIT();

    for (int kt = 0; kt < KT; kt++) {
        const int buf = kt % 3;
        if (kt + 1 < KT) CP_WAIT1(); else CP_WAIT0();
        __syncthreads();
        if (kt + 2 < KT) {
            LOAD_STAGE(kt + 2, (kt + 2) % 3);
            CP_COMMIT();
        }

#pragma unroll
        for (int ks = 0; ks < 2; ks++) {
            uint32_t af[4][4];
#pragma unroll
            for (int mt = 0; mt < 4; mt++) {
                uint32_t addr = sA[buf] + (a_row + mt * 16) * ROWB +
                                (ks * 16 + a_koff) * 2;
                ldsm_x4(af[mt][0], af[mt][1], af[mt][2], af[mt][3], addr);
            }
            uint32_t bfr[4][2];
#pragma unroll
            for (int p = 0; p < 2; p++) {
                uint32_t r0, r1, r2, r3;
                uint32_t addr = sB[buf] + (b_row + p * 16) * ROWB +
                                (ks * 16 + b_koff) * 2;
                ldsm_x4(r0, r1, r2, r3, addr);
                bfr[2 * p][0] = r0; bfr[2 * p][1] = r1;
                bfr[2 * p + 1][0] = r2; bfr[2 * p + 1][1] = r3;
            }
#pragma unroll
            for (int mt = 0; mt < 4; mt++)
#pragma unroll
                for (int nt = 0; nt < 4; nt++)
                    mma16816(acc[mt][nt], af[mt], bfr[nt]);
        }
        __syncthreads();
    }

    // epilogue
#pragma unroll
    for (int mt = 0; mt < 4; mt++) {
        const int rm = m0 + warp_m * 64 + mt * 16 + (lane >> 2);
#pragma unroll
        for (int nt = 0; nt < 4; nt++) {
            const int cn = n0 + warp_n * 32 + nt * 8 + ((lane & 3) << 1);
            const float b0 = bias[cn], b1 = bias[cn + 1];
            float2 v0, v1;
            v0.x = acc[mt][nt][0] + b0;
            v0.y = acc[mt][nt][1] + b1;
            v1.x = acc[mt][nt][2] + b0;
            v1.y = acc[mt][nt][3] + b1;
            if (relu) {
                v0.x = fmaxf(v0.x, 0.0f); v0.y = fmaxf(v0.y, 0.0f);
                v1.x = fmaxf(v1.x, 0.0f); v1.y = fmaxf(v1.y, 0.0f);
            }
            if (HALF_OUT) {
                __half* Ch = (__half*)Cout;
                *(__half2*)&Ch[(size_t)rm * HID + cn] = __floats2half2_rn(v0.x, v0.y);
                *(__half2*)&Ch[(size_t)(rm + 8) * HID + cn] = __floats2half2_rn(v1.x, v1.y);
            } else {
                float* Cf = (float*)Cout;
                *(float2*)&Cf[(size_t)rm * HID + cn] = v0;
                *(float2*)&Cf[(size_t)(rm + 8) * HID + cn] = v1;
            }
        }
    }
}

// ---------------------------------------------------------------------------
extern "C" void kernel_launch(void* const* d_in, const int* in_sizes, int n_in,
                              void* d_out, int out_size) {
    const float* node_in = (const float*)d_in[0];
    const int*   edges   = (const int*)d_in[1];
    const float* W_emb   = (const float*)d_in[2];
    const float* b_emb   = (const float*)d_in[3];
    const float* W1      = (const float*)d_in[4];
    const float* b1      = (const float*)d_in[5];
    const float* W2      = (const float*)d_in[6];
    const float* b2      = (const float*)d_in[7];
    const float* W3      = (const float*)d_in[8];
    const float* b3      = (const float*)d_in[9];
    float* out = (float*)d_out;

    __half* HA; cudaGetSymbolAddress((void**)&HA, g_HA);
    __half* HB; cudaGetSymbolAddress((void**)&HB, g_HB);
    __half* W;  cudaGetSymbolAddress((void**)&W, g_W);

    cudaFuncSetAttribute(gemm_hmma_kernel<HID, true>,
                         cudaFuncAttributeMaxDynamicSharedMemorySize, GSMEM);
    cudaFuncSetAttribute(gemm_hmma_kernel<HID, false>,
                         cudaFuncAttributeMaxDynamicSharedMemorySize, GSMEM);
    cudaFuncSetAttribute(gemm_hmma_kernel<F_NODE, true>,
                         cudaFuncAttributeMaxDynamicSharedMemorySize, GSMEM);

    deg_kernel<<<(N_NODES + 255) / 256, 256>>>(edges);
    convert_in_kernel<<<512, 256>>>(node_in);
    {
        dim3 tb(32, 8);
        wconvE_kernel<<<dim3(HID / 32, F_NODE / 32), tb>>>(W_emb, W + WOFF_E);
        wconv3_kernel<<<dim3(HID / 32, HID / 32, 3), tb>>>(W1, W2, W3, W + WOFF_1);
    }

    dim3 gg(HID / BN, N_NODES / BM);  // (4, 64)

    // embed: HB = node_in @ W_emb + b_emb  (fp16 out)
    gemm_hmma_kernel<F_NODE, true><<<gg, GTHR, GSMEM>>>(HA, W + WOFF_E, b_emb, HB, 0);
    // layer 1
    spmm_kernel<<<N_NODES, 128>>>(edges, HB, HA);
    gemm_hmma_kernel<HID, true><<<gg, GTHR, GSMEM>>>(HA, W + WOFF_1, b1, HB, 1);
    // layer 2
    spmm_kernel<<<N_NODES, 128>>>(edges, HB, HA);
    gemm_hmma_kernel<HID, true><<<gg, GTHR, GSMEM>>>(HA, W + WOFF_2, b2, HB, 1);
    // layer 3 -> fp32 out
    spmm_kernel<<<N_NODES, 128>>>(edges, HB, HA);
    gemm_hmma_kernel<HID, false><<<gg, GTHR, GSMEM>>>(HA, W + WOFF_3, b3, out, 0);
}

// round 8
// speedup vs baseline: 4.5673x; 1.0462x over previous
#include <cuda_runtime.h>
#include <cuda_fp16.h>
#include <cstdint>

#define N_NODES 8192
#define M_NBR   16
#define F_NODE  128
#define HID     512

// ---------------- scratch (__device__ globals; no allocations) ----------------
__device__ __half g_HA[N_NODES * HID];   // activation ping
__device__ __half g_HB[N_NODES * HID];   // activation pong
__device__ float  g_dinv[N_NODES];
#define WOFF_1 0
#define WOFF_2 (HID * HID)
#define WOFF_3 (2 * HID * HID)
#define WOFF_E (3 * HID * HID)
__device__ __half g_W[3 * HID * HID + HID * F_NODE];

// ---------------- PTX helpers (compute_103-safe) ----------------
__device__ __forceinline__ uint32_t smem_to_u32(const void* p) {
    uint32_t a;
    asm("{ .reg .u64 t; cvta.to.shared.u64 t, %1; cvt.u32.u64 %0, t; }" : "=r"(a) : "l"(p));
    return a;
}
__device__ __forceinline__ void cp_async16(uint32_t saddr, const void* gptr) {
    asm volatile("cp.async.cg.shared.global [%0], [%1], 16;" :: "r"(saddr), "l"(gptr));
}
#define CP_COMMIT() asm volatile("cp.async.commit_group;" ::: "memory")
#define CP_WAIT0()  asm volatile("cp.async.wait_group 0;" ::: "memory")
#define CP_WAIT1()  asm volatile("cp.async.wait_group 1;" ::: "memory")

__device__ __forceinline__ void ldsm_x4(uint32_t& r0, uint32_t& r1, uint32_t& r2,
                                        uint32_t& r3, uint32_t addr) {
    asm volatile("ldmatrix.sync.aligned.m8n8.x4.shared.b16 {%0,%1,%2,%3}, [%4];"
                 : "=r"(r0), "=r"(r1), "=r"(r2), "=r"(r3) : "r"(addr));
}
__device__ __forceinline__ void mma16816(float* d, const uint32_t* a, const uint32_t* b) {
    asm volatile(
        "mma.sync.aligned.m16n8k16.row.col.f32.f16.f16.f32 "
        "{%0,%1,%2,%3}, {%4,%5,%6,%7}, {%8,%9}, {%0,%1,%2,%3};"
        : "+f"(d[0]), "+f"(d[1]), "+f"(d[2]), "+f"(d[3])
        : "r"(a[0]), "r"(a[1]), "r"(a[2]), "r"(a[3]), "r"(b[0]), "r"(b[1]));
}

// ---------------------------------------------------------------------------
// Fused preprocessing (one launch):
//   blocks [0, 32)            : deg -> dinv
//   blocks [32, 1056)         : node_in fp32 -> g_HA fp16 (float4 chunks)
//   blocks [1056, 1120)       : W_emb transpose -> g_W[WOFF_E]
//   blocks [1120, 1888)       : W1/W2/W3 transpose -> g_W[WOFF_1..]
// ---------------------------------------------------------------------------
#define PREP_DEG    32
#define PREP_CONV   1024
#define PREP_WE     64       // (HID/32)*(F_NODE/32)
#define PREP_W3     768      // (HID/32)*(HID/32)*3
#define PREP_BLOCKS (PREP_DEG + PREP_CONV + PREP_WE + PREP_W3)

__device__ __forceinline__ void wconv_tile(const float* __restrict__ W, int K, int N,
                                           __half* __restrict__ o,
                                           int n0, int k0, int tx, int ty,
                                           float (*tile)[33]) {
#pragma unroll
    for (int r = 0; r < 4; r++) {
        int k = k0 + ty + r * 8;
        tile[ty + r * 8][tx] = W[(size_t)k * N + n0 + tx];
    }
    __syncthreads();
#pragma unroll
    for (int r = 0; r < 4; r++) {
        int n = ty + r * 8;
        o[(size_t)(n0 + n) * K + k0 + tx] = __float2half_rn(tile[tx][n]);
    }
}

__global__ __launch_bounds__(256) void prep_kernel(const int* __restrict__ idx,
                                                   const float* __restrict__ node_in,
                                                   const float* __restrict__ W_emb,
                                                   const float* __restrict__ W1,
                                                   const float* __restrict__ W2,
                                                   const float* __restrict__ W3) {
    __shared__ float tile[32][33];
    const int b = blockIdx.x;
    const int tid = threadIdx.x;

    if (b < PREP_DEG) {
        int i = b * 256 + tid;
        int cnt = 1;
#pragma unroll
        for (int k = 0; k < M_NBR; k++) cnt += (idx[i * M_NBR + k] >= 0) ? 1 : 0;
        g_dinv[i] = rsqrtf((float)cnt);
    } else if (b < PREP_DEG + PREP_CONV) {
        int c4 = (b - PREP_DEG) * 256 + tid;      // float4 chunk id, total 1M/4
        float4 v = ((const float4*)node_in)[c4];
        __half2 h0 = __floats2half2_rn(v.x, v.y);
        __half2 h1 = __floats2half2_rn(v.z, v.w);
        uint2 o;
        o.x = *(uint32_t*)&h0;
        o.y = *(uint32_t*)&h1;
        ((uint2*)g_HA)[c4] = o;
    } else if (b < PREP_DEG + PREP_CONV + PREP_WE) {
        int t = b - (PREP_DEG + PREP_CONV);
        int n0 = (t & 15) * 32, k0 = (t >> 4) * 32;
        wconv_tile(W_emb, F_NODE, HID, g_W + WOFF_E, n0, k0, tid & 31, tid >> 5, tile);
    } else {
        int t = b - (PREP_DEG + PREP_CONV + PREP_WE);
        int z = t >> 8;                 // 0..2
        int tt = t & 255;
        int n0 = (tt & 15) * 32, k0 = (tt >> 4) * 32;
        const float* W = (z == 0) ? W1 : (z == 1) ? W2 : W3;
        wconv_tile(W, HID, HID, g_W + (size_t)z * HID * HID, n0, k0,
                   tid & 31, tid >> 5, tile);
    }
}

// ---------------------------------------------------------------------------
// SpMM (fp16 in/out, fp32 accumulate), branch-free full-MLP gathers.
//   Y[i,:] = di * ( di*X[i,:] + sum_k dj_k*X[j_k,:] )   (dj=0 for invalid)
// 256 threads = 4 rows x 64 lanes; 16 B (8 halves) per lane.
// ---------------------------------------------------------------------------
__global__ __launch_bounds__(256) void spmm_kernel(const int* __restrict__ idx,
                                                   const __half* __restrict__ Xin,
                                                   __half* __restrict__ Xout) {
    const int rloc = threadIdx.x >> 6;           // 0..3
    const int t64 = threadIdx.x & 63;            // lane within row
    const int i = blockIdx.x * 4 + rloc;

    __shared__ int s_j[4][M_NBR];
    __shared__ float s_dj[4][M_NBR];
    if (t64 < M_NBR) {
        int j = idx[i * M_NBR + t64];
        s_j[rloc][t64] = (j >= 0) ? j : 0;       // clamp: load row 0, weight 0
        s_dj[rloc][t64] = (j >= 0) ? g_dinv[j] : 0.0f;
    }
    __syncthreads();

    const float di = g_dinv[i];
    float acc[8];
    {
        uint4 v = ((const uint4*)(Xin + (size_t)i * HID))[t64];
        float2 p0 = __half22float2(*(__half2*)&v.x);
        float2 p1 = __half22float2(*(__half2*)&v.y);
        float2 p2 = __half22float2(*(__half2*)&v.z);
        float2 p3 = __half22float2(*(__half2*)&v.w);
        acc[0] = p0.x * di; acc[1] = p0.y * di;
        acc[2] = p1.x * di; acc[3] = p1.y * di;
        acc[4] = p2.x * di; acc[5] = p2.y * di;
        acc[6] = p3.x * di; acc[7] = p3.y * di;
    }

#pragma unroll
    for (int k = 0; k < M_NBR; k++) {
        const int j = s_j[rloc][k];
        const float dj = s_dj[rloc][k];
        uint4 v = ((const uint4*)(Xin + (size_t)j * HID))[t64];
        float2 p0 = __half22float2(*(__half2*)&v.x);
        float2 p1 = __half22float2(*(__half2*)&v.y);
        float2 p2 = __half22float2(*(__half2*)&v.z);
        float2 p3 = __half22float2(*(__half2*)&v.w);
        acc[0] += dj * p0.x; acc[1] += dj * p0.y;
        acc[2] += dj * p1.x; acc[3] += dj * p1.y;
        acc[4] += dj * p2.x; acc[5] += dj * p2.y;
        acc[6] += dj * p3.x; acc[7] += dj * p3.y;
    }

    uint4 o;
    __half2 h0 = __floats2half2_rn(acc[0] * di, acc[1] * di);
    __half2 h1 = __floats2half2_rn(acc[2] * di, acc[3] * di);
    __half2 h2 = __floats2half2_rn(acc[4] * di, acc[5] * di);
    __half2 h3 = __floats2half2_rn(acc[6] * di, acc[7] * di);
    o.x = *(uint32_t*)&h0;
    o.y = *(uint32_t*)&h1;
    o.z = *(uint32_t*)&h2;
    o.w = *(uint32_t*)&h3;
    ((uint4*)(Xout + (size_t)i * HID))[t64] = o;
}

// ---------------------------------------------------------------------------
// fp16 HMMA GEMM: C[M x 512] = A[M x K] * B[512 x K]^T + bias (+relu)
// Output fp16 (intermediate) or fp32 (final) via template.
// BM=128 BN=128 BK=32, 256 thr, warp grid 2x4, 3-stage cp.async, pad-40 rows.
// ---------------------------------------------------------------------------
#define BM 128
#define BN 128
#define BK 32
#define GTHR 256
#define RPAD 40
#define ROWB 80
#define STAGE_B (2 * BM * RPAD * 2)   // 20480 B per stage (As+Bs)
#define GSMEM   (3 * STAGE_B)         // 61440 B

template <int K, bool HALF_OUT>
__global__ __launch_bounds__(GTHR, 2)
void gemm_hmma_kernel(const __half* __restrict__ A,
                      const __half* __restrict__ B,
                      const float* __restrict__ bias,
                      void* __restrict__ Cout, int relu) {
    extern __shared__ __align__(16) char dynsmem[];

    const int tid = threadIdx.x;
    const int lane = tid & 31;
    const int wid = tid >> 5;
    const int warp_m = wid >> 2;
    const int warp_n = wid & 3;
    const int m0 = blockIdx.y * BM;
    const int n0 = blockIdx.x * BN;

    uint32_t sA[3], sB[3];
#pragma unroll
    for (int s = 0; s < 3; s++) {
        sA[s] = smem_to_u32(dynsmem + s * STAGE_B);
        sB[s] = sA[s] + BM * ROWB;
    }

    float acc[4][4][4];
#pragma unroll
    for (int i = 0; i < 4; i++)
#pragma unroll
        for (int j = 0; j < 4; j++)
#pragma unroll
            for (int q = 0; q < 4; q++) acc[i][j][q] = 0.0f;

    constexpr int KT = K / BK;

    const int mat = lane >> 3;
    const int mrow = lane & 7;
    const int a_row = warp_m * 64 + ((mat & 1) << 3) + mrow;
    const int a_koff = (mat >> 1) << 3;
    const int b_row = warp_n * 32 + ((mat >> 1) << 3) + mrow;
    const int b_koff = (mat & 1) << 3;

    const int lr = tid >> 2;   // 0..63
    const int lc = tid & 3;    // 0..3

#define LOAD_STAGE(kt, buf)                                                     \
    do {                                                                        \
        const int kk_ = (kt) * BK;                                              \
        cp_async16(sA[buf] + lr * ROWB + lc * 16,                               \
                   A + (size_t)(m0 + lr) * K + kk_ + lc * 8);                   \
        cp_async16(sA[buf] + (lr + 64) * ROWB + lc * 16,                        \
                   A + (size_t)(m0 + lr + 64) * K + kk_ + lc * 8);              \
        cp_async16(sB[buf] + lr * ROWB + lc * 16,                               \
                   B + (size_t)(n0 + lr) * K + kk_ + lc * 8);                   \
        cp_async16(sB[buf] + (lr + 64) * ROWB + lc * 16,                        \
                   B + (size_t)(n0 + lr + 64) * K + kk_ + lc * 8);              \
    } while (0)

    LOAD_STAGE(0, 0);
    CP_COMMIT();
    LOAD_STAGE(1, 1);
    CP_COMMIT();

    for (int kt = 0; kt < KT; kt++) {
        const int buf = kt % 3;
        if (kt + 1 < KT) CP_WAIT1(); else CP_WAIT0();
        __syncthreads();
        if (kt + 2 < KT) {
            LOAD_STAGE(kt + 2, (kt + 2) % 3);
            CP_COMMIT();
        }

#pragma unroll
        for (int ks = 0; ks < 2; ks++) {
            uint32_t af[4][4];
#pragma unroll
            for (int mt = 0; mt < 4; mt++) {
                uint32_t addr = sA[buf] + (a_row + mt * 16) * ROWB +
                                (ks * 16 + a_koff) * 2;
                ldsm_x4(af[mt][0], af[mt][1], af[mt][2], af[mt][3], addr);
            }
            uint32_t bfr[4][2];
#pragma unroll
            for (int p = 0; p < 2; p++) {
                uint32_t r0, r1, r2, r3;
                uint32_t addr = sB[buf] + (b_row + p * 16) * ROWB +
                                (ks * 16 + b_koff) * 2;
                ldsm_x4(r0, r1, r2, r3, addr);
                bfr[2 * p][0] = r0; bfr[2 * p][1] = r1;
                bfr[2 * p + 1][0] = r2; bfr[2 * p + 1][1] = r3;
            }
#pragma unroll
            for (int mt = 0; mt < 4; mt++)
#pragma unroll
                for (int nt = 0; nt < 4; nt++)
                    mma16816(acc[mt][nt], af[mt], bfr[nt]);
        }
        __syncthreads();
    }

    // epilogue
#pragma unroll
    for (int mt = 0; mt < 4; mt++) {
        const int rm = m0 + warp_m * 64 + mt * 16 + (lane >> 2);
#pragma unroll
        for (int nt = 0; nt < 4; nt++) {
            const int cn = n0 + warp_n * 32 + nt * 8 + ((lane & 3) << 1);
            const float b0 = bias[cn], b1 = bias[cn + 1];
            float2 v0, v1;
            v0.x = acc[mt][nt][0] + b0;
            v0.y = acc[mt][nt][1] + b1;
            v1.x = acc[mt][nt][2] + b0;
            v1.y = acc[mt][nt][3] + b1;
            if (relu) {
                v0.x = fmaxf(v0.x, 0.0f); v0.y = fmaxf(v0.y, 0.0f);
                v1.x = fmaxf(v1.x, 0.0f); v1.y = fmaxf(v1.y, 0.0f);
            }
            if (HALF_OUT) {
                __half* Ch = (__half*)Cout;
                *(__half2*)&Ch[(size_t)rm * HID + cn] = __floats2half2_rn(v0.x, v0.y);
                *(__half2*)&Ch[(size_t)(rm + 8) * HID + cn] = __floats2half2_rn(v1.x, v1.y);
            } else {
                float* Cf = (float*)Cout;
                *(float2*)&Cf[(size_t)rm * HID + cn] = v0;
                *(float2*)&Cf[(size_t)(rm + 8) * HID + cn] = v1;
            }
        }
    }
}

// ---------------------------------------------------------------------------
extern "C" void kernel_launch(void* const* d_in, const int* in_sizes, int n_in,
                              void* d_out, int out_size) {
    const float* node_in = (const float*)d_in[0];
    const int*   edges   = (const int*)d_in[1];
    const float* W_emb   = (const float*)d_in[2];
    const float* b_emb   = (const float*)d_in[3];
    const float* W1      = (const float*)d_in[4];
    const float* b1      = (const float*)d_in[5];
    const float* W2      = (const float*)d_in[6];
    const float* b2      = (const float*)d_in[7];
    const float* W3      = (const float*)d_in[8];
    const float* b3      = (const float*)d_in[9];
    float* out = (float*)d_out;

    __half* HA; cudaGetSymbolAddress((void**)&HA, g_HA);
    __half* HB; cudaGetSymbolAddress((void**)&HB, g_HB);
    __half* W;  cudaGetSymbolAddress((void**)&W, g_W);

    cudaFuncSetAttribute(gemm_hmma_kernel<HID, true>,
                         cudaFuncAttributeMaxDynamicSharedMemorySize, GSMEM);
    cudaFuncSetAttribute(gemm_hmma_kernel<HID, false>,
                         cudaFuncAttributeMaxDynamicSharedMemorySize, GSMEM);
    cudaFuncSetAttribute(gemm_hmma_kernel<F_NODE, true>,
                         cudaFuncAttributeMaxDynamicSharedMemorySize, GSMEM);

    // one fused preprocessing launch
    prep_kernel<<<PREP_BLOCKS, 256>>>(edges, node_in, W_emb, W1, W2, W3);

    dim3 gg(HID / BN, N_NODES / BM);  // (4, 64)

    // embed: HB = node_in @ W_emb + b_emb  (fp16 out)
    gemm_hmma_kernel<F_NODE, true><<<gg, GTHR, GSMEM>>>(HA, W + WOFF_E, b_emb, HB, 0);
    // layer 1
    spmm_kernel<<<N_NODES / 4, 256>>>(edges, HB, HA);
    gemm_hmma_kernel<HID, true><<<gg, GTHR, GSMEM>>>(HA, W + WOFF_1, b1, HB, 1);
    // layer 2
    spmm_kernel<<<N_NODES / 4, 256>>>(edges, HB, HA);
    gemm_hmma_kernel<HID, true><<<gg, GTHR, GSMEM>>>(HA, W + WOFF_2, b2, HB, 1);
    // layer 3 -> fp32 out
    spmm_kernel<<<N_NODES / 4, 256>>>(edges, HB, HA);
    gemm_hmma_kernel<HID, false><<<gg, GTHR, GSMEM>>>(HA, W + WOFF_3, b3, out, 0);
}

// round 9
// speedup vs baseline: 4.6444x; 1.0169x over previous
#include <cuda_runtime.h>
#include <cuda_fp16.h>
#include <cstdint>

#define N_NODES 8192
#define M_NBR   16
#define F_NODE  128
#define HID     512

// ---------------- scratch (__device__ globals; no allocations) ----------------
__device__ __half g_HA[N_NODES * HID];   // activation ping
__device__ __half g_HB[N_NODES * HID];   // activation pong
__device__ float  g_dinv[N_NODES];
#define WOFF_1 0
#define WOFF_2 (HID * HID)
#define WOFF_3 (2 * HID * HID)
#define WOFF_E (3 * HID * HID)
__device__ __half g_W[3 * HID * HID + HID * F_NODE];

// ---------------- PTX helpers (compute_103-safe) ----------------
__device__ __forceinline__ uint32_t smem_to_u32(const void* p) {
    uint32_t a;
    asm("{ .reg .u64 t; cvta.to.shared.u64 t, %1; cvt.u32.u64 %0, t; }" : "=r"(a) : "l"(p));
    return a;
}
__device__ __forceinline__ void cp_async16(uint32_t saddr, const void* gptr) {
    asm volatile("cp.async.cg.shared.global [%0], [%1], 16;" :: "r"(saddr), "l"(gptr));
}
#define CP_COMMIT() asm volatile("cp.async.commit_group;" ::: "memory")
#define CP_WAIT0()  asm volatile("cp.async.wait_group 0;" ::: "memory")
#define CP_WAIT1()  asm volatile("cp.async.wait_group 1;" ::: "memory")

__device__ __forceinline__ void ldsm_x4(uint32_t& r0, uint32_t& r1, uint32_t& r2,
                                        uint32_t& r3, uint32_t addr) {
    asm volatile("ldmatrix.sync.aligned.m8n8.x4.shared.b16 {%0,%1,%2,%3}, [%4];"
                 : "=r"(r0), "=r"(r1), "=r"(r2), "=r"(r3) : "r"(addr));
}
__device__ __forceinline__ void mma16816(float* d, const uint32_t* a, const uint32_t* b) {
    asm volatile(
        "mma.sync.aligned.m16n8k16.row.col.f32.f16.f16.f32 "
        "{%0,%1,%2,%3}, {%4,%5,%6,%7}, {%8,%9}, {%0,%1,%2,%3};"
        : "+f"(d[0]), "+f"(d[1]), "+f"(d[2]), "+f"(d[3])
        : "r"(a[0]), "r"(a[1]), "r"(a[2]), "r"(a[3]), "r"(b[0]), "r"(b[1]));
}

// ---------------------------------------------------------------------------
// Fused preprocessing (one launch):
//   blocks [0, 32)      : deg -> dinv
//   blocks [32, 1056)   : node_in fp32 -> g_HA fp16
//   blocks [1056, 1120) : W_emb transpose
//   blocks [1120, 1888) : W1/W2/W3 transpose
// ---------------------------------------------------------------------------
#define PREP_DEG    32
#define PREP_CONV   1024
#define PREP_WE     64
#define PREP_W3     768
#define PREP_BLOCKS (PREP_DEG + PREP_CONV + PREP_WE + PREP_W3)

__device__ __forceinline__ void wconv_tile(const float* __restrict__ W, int K, int N,
                                           __half* __restrict__ o,
                                           int n0, int k0, int tx, int ty,
                                           float (*tile)[33]) {
#pragma unroll
    for (int r = 0; r < 4; r++) {
        int k = k0 + ty + r * 8;
        tile[ty + r * 8][tx] = W[(size_t)k * N + n0 + tx];
    }
    __syncthreads();
#pragma unroll
    for (int r = 0; r < 4; r++) {
        int n = ty + r * 8;
        o[(size_t)(n0 + n) * K + k0 + tx] = __float2half_rn(tile[tx][n]);
    }
}

__global__ __launch_bounds__(256) void prep_kernel(const int* __restrict__ idx,
                                                   const float* __restrict__ node_in,
                                                   const float* __restrict__ W_emb,
                                                   const float* __restrict__ W1,
                                                   const float* __restrict__ W2,
                                                   const float* __restrict__ W3) {
    __shared__ float tile[32][33];
    const int b = blockIdx.x;
    const int tid = threadIdx.x;

    if (b < PREP_DEG) {
        int i = b * 256 + tid;
        int cnt = 1;
#pragma unroll
        for (int k = 0; k < M_NBR; k++) cnt += (idx[i * M_NBR + k] >= 0) ? 1 : 0;
        g_dinv[i] = rsqrtf((float)cnt);
    } else if (b < PREP_DEG + PREP_CONV) {
        int c4 = (b - PREP_DEG) * 256 + tid;
        float4 v = ((const float4*)node_in)[c4];
        __half2 h0 = __floats2half2_rn(v.x, v.y);
        __half2 h1 = __floats2half2_rn(v.z, v.w);
        uint2 o;
        o.x = *(uint32_t*)&h0;
        o.y = *(uint32_t*)&h1;
        ((uint2*)g_HA)[c4] = o;
    } else if (b < PREP_DEG + PREP_CONV + PREP_WE) {
        int t = b - (PREP_DEG + PREP_CONV);
        int n0 = (t & 15) * 32, k0 = (t >> 4) * 32;
        wconv_tile(W_emb, F_NODE, HID, g_W + WOFF_E, n0, k0, tid & 31, tid >> 5, tile);
    } else {
        int t = b - (PREP_DEG + PREP_CONV + PREP_WE);
        int z = t >> 8;
        int tt = t & 255;
        int n0 = (tt & 15) * 32, k0 = (tt >> 4) * 32;
        const float* W = (z == 0) ? W1 : (z == 1) ? W2 : W3;
        wconv_tile(W, HID, HID, g_W + (size_t)z * HID * HID, n0, k0,
                   tid & 31, tid >> 5, tile);
    }
}

// ---------------------------------------------------------------------------
// SpMM (fp16 in/out, fp32 accumulate), branch-free gathers.
// 256 threads = 4 rows x 64 lanes; 16 B per lane.
// ---------------------------------------------------------------------------
__global__ __launch_bounds__(256) void spmm_kernel(const int* __restrict__ idx,
                                                   const __half* __restrict__ Xin,
                                                   __half* __restrict__ Xout) {
    const int rloc = threadIdx.x >> 6;
    const int t64 = threadIdx.x & 63;
    const int i = blockIdx.x * 4 + rloc;

    __shared__ int s_j[4][M_NBR];
    __shared__ float s_dj[4][M_NBR];
    if (t64 < M_NBR) {
        int j = idx[i * M_NBR + t64];
        s_j[rloc][t64] = (j >= 0) ? j : 0;
        s_dj[rloc][t64] = (j >= 0) ? g_dinv[j] : 0.0f;
    }
    __syncthreads();

    const float di = g_dinv[i];
    float acc[8];
    {
        uint4 v = ((const uint4*)(Xin + (size_t)i * HID))[t64];
        float2 p0 = __half22float2(*(__half2*)&v.x);
        float2 p1 = __half22float2(*(__half2*)&v.y);
        float2 p2 = __half22float2(*(__half2*)&v.z);
        float2 p3 = __half22float2(*(__half2*)&v.w);
        acc[0] = p0.x * di; acc[1] = p0.y * di;
        acc[2] = p1.x * di; acc[3] = p1.y * di;
        acc[4] = p2.x * di; acc[5] = p2.y * di;
        acc[6] = p3.x * di; acc[7] = p3.y * di;
    }

#pragma unroll
    for (int k = 0; k < M_NBR; k++) {
        const int j = s_j[rloc][k];
        const float dj = s_dj[rloc][k];
        uint4 v = ((const uint4*)(Xin + (size_t)j * HID))[t64];
        float2 p0 = __half22float2(*(__half2*)&v.x);
        float2 p1 = __half22float2(*(__half2*)&v.y);
        float2 p2 = __half22float2(*(__half2*)&v.z);
        float2 p3 = __half22float2(*(__half2*)&v.w);
        acc[0] += dj * p0.x; acc[1] += dj * p0.y;
        acc[2] += dj * p1.x; acc[3] += dj * p1.y;
        acc[4] += dj * p2.x; acc[5] += dj * p2.y;
        acc[6] += dj * p3.x; acc[7] += dj * p3.y;
    }

    uint4 o;
    __half2 h0 = __floats2half2_rn(acc[0] * di, acc[1] * di);
    __half2 h1 = __floats2half2_rn(acc[2] * di, acc[3] * di);
    __half2 h2 = __floats2half2_rn(acc[4] * di, acc[5] * di);
    __half2 h3 = __floats2half2_rn(acc[6] * di, acc[7] * di);
    o.x = *(uint32_t*)&h0;
    o.y = *(uint32_t*)&h1;
    o.z = *(uint32_t*)&h2;
    o.w = *(uint32_t*)&h3;
    ((uint4*)(Xout + (size_t)i * HID))[t64] = o;
}

// ---------------------------------------------------------------------------
// fp16 HMMA GEMM: C[M x 512] = A[M x K] * B[512 x K]^T + bias (+relu)
// BM=128 BN=128 BK=64, 256 thr, warp grid 2x4 (warp tile 64x32),
// 3-stage cp.async, ONE __syncthreads per k-iteration, pad-72 rows (144 B).
// ---------------------------------------------------------------------------
#define BM 128
#define BN 128
#define BK 64
#define GTHR 256
#define ROWB 144                       // 64*2 + 16 pad bytes
#define STAGE_B (2 * BM * ROWB)        // As+Bs per stage = 36864 B
#define GSMEM   (3 * STAGE_B)          // 110592 B

template <int K, bool HALF_OUT>
__global__ __launch_bounds__(GTHR, 2)
void gemm_hmma_kernel(const __half* __restrict__ A,
                      const __half* __restrict__ B,
                      const float* __restrict__ bias,
                      void* __restrict__ Cout, int relu) {
    extern __shared__ __align__(16) char dynsmem[];

    const int tid = threadIdx.x;
    const int lane = tid & 31;
    const int wid = tid >> 5;
    const int warp_m = wid >> 2;
    const int warp_n = wid & 3;
    const int m0 = blockIdx.y * BM;
    const int n0 = blockIdx.x * BN;

    uint32_t sA[3], sB[3];
#pragma unroll
    for (int s = 0; s < 3; s++) {
        sA[s] = smem_to_u32(dynsmem + s * STAGE_B);
        sB[s] = sA[s] + BM * ROWB;
    }

    float acc[4][4][4];
#pragma unroll
    for (int i = 0; i < 4; i++)
#pragma unroll
        for (int j = 0; j < 4; j++)
#pragma unroll
            for (int q = 0; q < 4; q++) acc[i][j][q] = 0.0f;

    constexpr int KT = K / BK;

    const int mat = lane >> 3;
    const int mrow = lane & 7;
    const int a_row = warp_m * 64 + ((mat & 1) << 3) + mrow;
    const int a_koff = (mat >> 1) << 3;
    const int b_row = warp_n * 32 + ((mat >> 1) << 3) + mrow;
    const int b_koff = (mat & 1) << 3;

    // loads: 128 rows x 8 chunks (16B) per operand = 1024 chunks, 4 per thread
    const int lr = tid >> 3;        // 0..31 (row group base)
    const int lc = tid & 7;         // chunk in row

#define LOAD_STAGE(kt, buf)                                                     \
    do {                                                                        \
        const int kk_ = (kt) * BK;                                              \
        _Pragma("unroll")                                                       \
        for (int s_ = 0; s_ < 4; s_++) {                                        \
            int r_ = lr + s_ * 32;                                              \
            cp_async16(sA[buf] + r_ * ROWB + lc * 16,                           \
                       A + (size_t)(m0 + r_) * K + kk_ + lc * 8);               \
            cp_async16(sB[buf] + r_ * ROWB + lc * 16,                           \
                       B + (size_t)(n0 + r_) * K + kk_ + lc * 8);               \
        }                                                                       \
    } while (0)

    LOAD_STAGE(0, 0);
    CP_COMMIT();
    LOAD_STAGE(1, 1);
    CP_COMMIT();

    for (int kt = 0; kt < KT; kt++) {
        const int buf = kt % 3;
        if (kt + 1 < KT) CP_WAIT1(); else CP_WAIT0();
        __syncthreads();
        if (kt + 2 < KT) {
            LOAD_STAGE(kt + 2, (kt + 2) % 3);
            CP_COMMIT();
        }

#pragma unroll
        for (int ks = 0; ks < BK / 16; ks++) {
            uint32_t af[4][4];
#pragma unroll
            for (int mt = 0; mt < 4; mt++) {
                uint32_t addr = sA[buf] + (a_row + mt * 16) * ROWB +
                                (ks * 16 + a_koff) * 2;
                ldsm_x4(af[mt][0], af[mt][1], af[mt][2], af[mt][3], addr);
            }
            uint32_t bfr[4][2];
#pragma unroll
            for (int p = 0; p < 2; p++) {
                uint32_t r0, r1, r2, r3;
                uint32_t addr = sB[buf] + (b_row + p * 16) * ROWB +
                                (ks * 16 + b_koff) * 2;
                ldsm_x4(r0, r1, r2, r3, addr);
                bfr[2 * p][0] = r0; bfr[2 * p][1] = r1;
                bfr[2 * p + 1][0] = r2; bfr[2 * p + 1][1] = r3;
            }
#pragma unroll
            for (int mt = 0; mt < 4; mt++)
#pragma unroll
                for (int nt = 0; nt < 4; nt++)
                    mma16816(acc[mt][nt], af[mt], bfr[nt]);
        }
        // no trailing __syncthreads: next iteration's barrier orders buffer reuse
    }

    // epilogue
#pragma unroll
    for (int mt = 0; mt < 4; mt++) {
        const int rm = m0 + warp_m * 64 + mt * 16 + (lane >> 2);
#pragma unroll
        for (int nt = 0; nt < 4; nt++) {
            const int cn = n0 + warp_n * 32 + nt * 8 + ((lane & 3) << 1);
            const float b0 = bias[cn], b1 = bias[cn + 1];
            float2 v0, v1;
            v0.x = acc[mt][nt][0] + b0;
            v0.y = acc[mt][nt][1] + b1;
            v1.x = acc[mt][nt][2] + b0;
            v1.y = acc[mt][nt][3] + b1;
            if (relu) {
                v0.x = fmaxf(v0.x, 0.0f); v0.y = fmaxf(v0.y, 0.0f);
                v1.x = fmaxf(v1.x, 0.0f); v1.y = fmaxf(v1.y, 0.0f);
            }
            if (HALF_OUT) {
                __half* Ch = (__half*)Cout;
                *(__half2*)&Ch[(size_t)rm * HID + cn] = __floats2half2_rn(v0.x, v0.y);
                *(__half2*)&Ch[(size_t)(rm + 8) * HID + cn] = __floats2half2_rn(v1.x, v1.y);
            } else {
                float* Cf = (float*)Cout;
                *(float2*)&Cf[(size_t)rm * HID + cn] = v0;
                *(float2*)&Cf[(size_t)(rm + 8) * HID + cn] = v1;
            }
        }
    }
}

// ---------------------------------------------------------------------------
extern "C" void kernel_launch(void* const* d_in, const int* in_sizes, int n_in,
                              void* d_out, int out_size) {
    const float* node_in = (const float*)d_in[0];
    const int*   edges   = (const int*)d_in[1];
    const float* W_emb   = (const float*)d_in[2];
    const float* b_emb   = (const float*)d_in[3];
    const float* W1      = (const float*)d_in[4];
    const float* b1      = (const float*)d_in[5];
    const float* W2      = (const float*)d_in[6];
    const float* b2      = (const float*)d_in[7];
    const float* W3      = (const float*)d_in[8];
    const float* b3      = (const float*)d_in[9];
    float* out = (float*)d_out;

    __half* HA; cudaGetSymbolAddress((void**)&HA, g_HA);
    __half* HB; cudaGetSymbolAddress((void**)&HB, g_HB);
    __half* W;  cudaGetSymbolAddress((void**)&W, g_W);

    cudaFuncSetAttribute(gemm_hmma_kernel<HID, true>,
                         cudaFuncAttributeMaxDynamicSharedMemorySize, GSMEM);
    cudaFuncSetAttribute(gemm_hmma_kernel<HID, false>,
                         cudaFuncAttributeMaxDynamicSharedMemorySize, GSMEM);
    cudaFuncSetAttribute(gemm_hmma_kernel<F_NODE, true>,
                         cudaFuncAttributeMaxDynamicSharedMemorySize, GSMEM);

    prep_kernel<<<PREP_BLOCKS, 256>>>(edges, node_in, W_emb, W1, W2, W3);

    dim3 gg(HID / BN, N_NODES / BM);  // (4, 64)

    // embed: HB = node_in @ W_emb + b_emb  (fp16 out)
    gemm_hmma_kernel<F_NODE, true><<<gg, GTHR, GSMEM>>>(HA, W + WOFF_E, b_emb, HB, 0);
    // layer 1
    spmm_kernel<<<N_NODES / 4, 256>>>(edges, HB, HA);
    gemm_hmma_kernel<HID, true><<<gg, GTHR, GSMEM>>>(HA, W + WOFF_1, b1, HB, 1);
    // layer 2
    spmm_kernel<<<N_NODES / 4, 256>>>(edges, HB, HA);
    gemm_hmma_kernel<HID, true><<<gg, GTHR, GSMEM>>>(HA, W + WOFF_2, b2, HB, 1);
    // layer 3 -> fp32 out
    spmm_kernel<<<N_NODES / 4, 256>>>(edges, HB, HA);
    gemm_hmma_kernel<HID, false><<<gg, GTHR, GSMEM>>>(HA, W + WOFF_3, b3, out, 0);
}